// round 6
// baseline (speedup 1.0000x reference)
#include <cuda_runtime.h>
#include <cuda_bf16.h>
#include <cstdint>

#define BATCH 4
#define NPTS 8192
#define KNN 16
#define NP_TOTAL (BATCH * NPTS)

typedef unsigned long long ull;

#define NCH1 33   // conv1: 259 ch -> 33 chunks of 8 ch (64 f)
#define NCH2 17   // conv2: 131 ch -> 17 chunks
#define ROWW 40   // padded row stride in words (80 bf16 = 160B)
#define CHUNK_WORDS 10240   // per-chunk B image: 2 halves x 128 rows x 40 words

__device__ float g_fcat1[NP_TOTAL * 260];   // [p][256 feat | 3 xyz | pad]
__device__ float g_fcat2[NP_TOTAL * 132];   // [p][128 feat | 3 xyz | pad]
__device__ float g_f2[NP_TOTAL * 128];
__device__ uint32_t g_B1[NCH1 * CHUNK_WORDS];
__device__ uint32_t g_B2[NCH2 * CHUNK_WORDS];
__device__ float g_w1t[128 * 128];
__device__ float g_w2t[128 * 64];

__device__ __forceinline__ float lrelu(float v) { return v >= 0.f ? v : 0.1f * v; }
__device__ __forceinline__ ull ffma2(ull a, ull b, ull c) {
    ull d; asm("fma.rn.f32x2 %0, %1, %2, %3;" : "=l"(d) : "l"(a), "l"(b), "l"(c)); return d;
}
__device__ __forceinline__ ull dup2(float x) {
    ull d; asm("mov.b64 %0, {%1, %1};" : "=l"(d) : "f"(x)); return d;
}
__device__ __forceinline__ float2 unpk(ull v) {
    float2 r; asm("mov.b64 {%0, %1}, %2;" : "=f"(r.x), "=f"(r.y) : "l"(v)); return r;
}
__device__ __forceinline__ uint32_t pack_bf16(float a, float b) {
    __nv_bfloat162 h = __floats2bfloat162_rn(a, b);
    return *(uint32_t*)&h;
}

__device__ __forceinline__ void mma_bf16(float* c, uint32_t a0, uint32_t a1,
                                         uint32_t a2, uint32_t a3,
                                         uint32_t b0, uint32_t b1) {
    asm volatile(
        "mma.sync.aligned.m16n8k16.row.col.f32.bf16.bf16.f32 "
        "{%0,%1,%2,%3}, {%4,%5,%6,%7}, {%8,%9}, {%0,%1,%2,%3};"
        : "+f"(c[0]), "+f"(c[1]), "+f"(c[2]), "+f"(c[3])
        : "r"(a0), "r"(a1), "r"(a2), "r"(a3), "r"(b0), "r"(b1));
}

// ---------------- prep ----------------------------------------------------------
__global__ void prep_weights(const float* __restrict__ wm1, const float* __restrict__ wm2) {
    int i = blockIdx.x * blockDim.x + threadIdx.x;
    if (i < 128 * 128) { int c = i >> 7, o = i & 127; g_w1t[i] = wm1[o * 128 + c]; }
    if (i < 128 * 64)  { int o = i >> 6, j = i & 63;  g_w2t[i] = wm2[j * 128 + o]; }
}

__global__ void prep_xyz(const float* __restrict__ xyz) {
    int i = blockIdx.x * blockDim.x + threadIdx.x;
    if (i >= NP_TOTAL * 3) return;
    int p = i / 3, d = i - p * 3;
    int b = p >> 13, n = p & (NPTS - 1);
    float v = xyz[((size_t)b * 3 + d) * NPTS + n];
    g_fcat1[(size_t)p * 260 + 256 + d] = v;
    g_fcat2[(size_t)p * 132 + 128 + d] = v;
}

__global__ void transpose_feat(const float* __restrict__ feat) {
    __shared__ float tile[32][33];
    int b = blockIdx.z;
    int n0 = blockIdx.x * 32, c0 = blockIdx.y * 32;
    int x = threadIdx.x, y = threadIdx.y;
    tile[y][x] = feat[((size_t)b * 256 + c0 + y) * NPTS + n0 + x];
    __syncthreads();
    g_fcat1[((size_t)(b * NPTS + n0 + y)) * 260 + c0 + x] = tile[x][y];
}

// col layout per k16 sub: pos(k) = (k&1) | (((k>>1)&3)<<2) | (((k>>3)&1)<<1)
__device__ __forceinline__ float fetch_w(const float* wl, int Freal, int CIN, int n,
                                         int ci, int col) {
    if (col >= 64) return 0.f;
    int s = col >> 4, pos = col & 15;
    int k = (pos & 1) | (((pos >> 2) & 3) << 1) | (((pos >> 1) & 1) << 3);
    int f = ci * 64 + s * 16 + k;
    int c = f >> 3, m = f & 7;
    if (c >= CIN + 3) return 0.f;
    int co = (c < CIN) ? c + 3 : c - CIN;
    return wl[n * Freal + co * 8 + m];
}

__global__ void prep_B(const float* __restrict__ wl1, const float* __restrict__ wl2) {
    int i = blockIdx.x * blockDim.x + threadIdx.x;
    if (i < NCH1 * CHUNK_WORDS) {
        int ci = i / CHUNK_WORDS, r = i % CHUNK_WORDS;
        int h = r / 5120, r2 = r % 5120;
        int n = r2 / ROWW, wc = r2 % ROWW;
        float v0 = fetch_w(wl1, 2072, 256, n, ci, 2 * wc);
        float v1 = fetch_w(wl1, 2072, 256, n, ci, 2 * wc + 1);
        float h0 = __bfloat162float(__float2bfloat16_rn(v0));
        float h1 = __bfloat162float(__float2bfloat16_rn(v1));
        g_B1[i] = h ? pack_bf16(v0 - h0, v1 - h1) : pack_bf16(h0, h1);
    }
    if (i < NCH2 * CHUNK_WORDS) {
        int ci = i / CHUNK_WORDS, r = i % CHUNK_WORDS;
        int h = r / 5120, r2 = r % 5120;
        int n = r2 / ROWW, wc = r2 % ROWW;
        float v0 = fetch_w(wl2, 1048, 128, n, ci, 2 * wc);
        float v1 = fetch_w(wl2, 1048, 128, n, ci, 2 * wc + 1);
        float h0 = __bfloat162float(__float2bfloat16_rn(v0));
        float h1 = __bfloat162float(__float2bfloat16_rn(v1));
        g_B2[i] = h ? pack_bf16(v0 - h0, v1 - h1) : pack_bf16(h0, h1);
    }
}

// ---------------- fused point-conv (pipelined mma.sync bf16 3-term) -------------
// dyn smem word offsets:
#define OFF_A   0            // A image: hi 5120 | lo 5120
#define OFF_B   10240        // B double buffer: 2 x 10240
#define OFF_W   30720        // s_w fp32 [128][128]
#define OFF_NBR 47104        // 2048 ints
#define OFF_CX  49152        // 384
#define OFF_BIAS 49536       // 128
#define DYN_WORDS 49664
#define DYN_BYTES (DYN_WORDS * 4)

template <int CIN, int STRIDE_IN>
__device__ __forceinline__ void produce_chunk(
    const float* __restrict__ fcat, const int* s_nbr, const float* s_w,
    int wid, int lane, int c0ch, uint32_t* apkH, uint32_t* apkL) {
    constexpr int CIN3 = CIN + 3;
#pragma unroll
    for (int pb = 0; pb < 4; ++pb) {
        const int pt = wid * 16 + pb * 4 + (lane >> 3);
        const int c  = lane & 7;
        const int cg = c0ch + c;
        const bool valid = (cg < CIN3);
        const int* np_ = s_nbr + pt * 16;
        const float* fp = fcat + cg;
        const ull* wp = (const ull*)(s_w + pt * 128);
        ull a0 = 0, a1 = 0, a2 = 0, a3 = 0;
#pragma unroll
        for (int k = 0; k < 16; ++k) {
            float fv = valid ? __ldg(fp + (size_t)np_[k] * STRIDE_IN) : 0.f;
            ull fd = dup2(fv);
            ulonglong2 w01 = *(const ulonglong2*)(wp + k * 4);
            ulonglong2 w23 = *(const ulonglong2*)(wp + k * 4 + 2);
            a0 = ffma2(fd, w01.x, a0);
            a1 = ffma2(fd, w01.y, a1);
            a2 = ffma2(fd, w23.x, a2);
            a3 = ffma2(fd, w23.y, a3);
        }
        float2 m01 = unpk(a0), m23 = unpk(a1), m45 = unpk(a2), m67 = unpk(a3);
        float v[8] = { m01.x, m01.y, m23.x, m23.y, m45.x, m45.y, m67.x, m67.y };
#pragma unroll
        for (int q = 0; q < 4; ++q) {
            float h0 = __bfloat162float(__float2bfloat16_rn(v[2 * q]));
            float h1 = __bfloat162float(__float2bfloat16_rn(v[2 * q + 1]));
            apkH[pb * 4 + q] = pack_bf16(h0, h1);
            apkL[pb * 4 + q] = pack_bf16(v[2 * q] - h0, v[2 * q + 1] - h1);
        }
    }
}

__device__ __forceinline__ void store_chunkA(
    uint32_t* sAH, uint32_t* sAL, int wid, int lane,
    const uint32_t* apkH, const uint32_t* apkL) {
#pragma unroll
    for (int pb = 0; pb < 4; ++pb) {
        const int pt = wid * 16 + pb * 4 + (lane >> 3);
        const int c  = lane & 7;
        const int slot = pt * ROWW + ((c >> 1) << 3) + (c & 1);
        sAH[slot + 0] = apkH[pb * 4 + 0];
        sAH[slot + 2] = apkH[pb * 4 + 1];
        sAH[slot + 4] = apkH[pb * 4 + 2];
        sAH[slot + 6] = apkH[pb * 4 + 3];
        sAL[slot + 0] = apkL[pb * 4 + 0];
        sAL[slot + 2] = apkL[pb * 4 + 1];
        sAL[slot + 4] = apkL[pb * 4 + 2];
        sAL[slot + 6] = apkL[pb * 4 + 3];
    }
}

template <int CIN, int STRIDE_IN, int OUT_STRIDE, int NCHUNK>
__global__ void __launch_bounds__(256, 1)
conv_mma(const float* __restrict__ fcat, const int* __restrict__ knn,
         const float* __restrict__ w_wn, const float* __restrict__ b_wn,
         const float* __restrict__ b_lin, const uint32_t* __restrict__ gB,
         float* __restrict__ out) {
    extern __shared__ float dyn[];
    uint32_t* sAH = (uint32_t*)dyn + OFF_A;
    uint32_t* sAL = sAH + 5120;
    uint32_t* sB0 = (uint32_t*)dyn + OFF_B;     // double buffer, stride CHUNK_WORDS
    float* s_w    = dyn + OFF_W;
    int*   s_nbr  = (int*)(dyn + OFF_NBR);
    float* s_cx   = dyn + OFF_CX;
    float* s_bias = dyn + OFF_BIAS;

    __shared__ float s_wn[24];
    __shared__ float s_bwn[8];

    const int tid  = threadIdx.x;
    const int wid  = tid >> 5, lane = tid & 31;
    const int g    = lane >> 2, t = lane & 3;
    const int base = blockIdx.x * 128;
    const int boff = (base >> 13) << 13;

    if (tid < 24) s_wn[tid] = w_wn[tid];
    if (tid < 8)  s_bwn[tid] = b_wn[tid];
    if (tid < 128) {
        s_bias[tid] = b_lin[tid];
        const float* cp = fcat + (size_t)(base + tid) * STRIDE_IN + CIN;
        s_cx[tid * 3 + 0] = cp[0];
        s_cx[tid * 3 + 1] = cp[1];
        s_cx[tid * 3 + 2] = cp[2];
    }
#pragma unroll
    for (int r = 0; r < 8; ++r) {
        int id = tid + r * 256;
        int pt = id >> 4, k = id & 15;
        s_nbr[id] = boff + knn[(size_t)(base + pt) * KNN + k];
    }
    __syncthreads();

    // weight-net into s_w[pt][k*8+m]
#pragma unroll
    for (int r = 0; r < 8; ++r) {
        int id = tid + r * 256;
        int pt = id >> 4, k = id & 15;
        int j = s_nbr[id];
        const float* nx = fcat + (size_t)j * STRIDE_IN + CIN;
        float px = nx[0] - s_cx[pt * 3 + 0];
        float py = nx[1] - s_cx[pt * 3 + 1];
        float pz = nx[2] - s_cx[pt * 3 + 2];
#pragma unroll
        for (int m = 0; m < 8; ++m) {
            float v = s_wn[m * 3 + 0] * px + s_wn[m * 3 + 1] * py +
                      s_wn[m * 3 + 2] * pz + s_bwn[m];
            s_w[pt * 128 + k * 8 + m] = lrelu(v);
        }
    }
    __syncthreads();

    float acc[64];
#pragma unroll
    for (int i = 0; i < 64; ++i) acc[i] = 0.f;

    // warp tile: rows rt*32..+31, cols ch*64..+63
    const int rt = wid & 3, ch = wid >> 2;
    const int rowA = rt * 32 + g;

    uint32_t apkH[16], apkL[16];

    // ---- prologue: chunk 0
    {
        const uint4* src = (const uint4*)(gB);
        uint4* dst = (uint4*)sB0;
        for (int i2 = tid; i2 < CHUNK_WORDS / 4; i2 += 256) dst[i2] = __ldg(src + i2);
        produce_chunk<CIN, STRIDE_IN>(fcat, s_nbr, s_w, wid, lane, 0, apkH, apkL);
        store_chunkA(sAH, sAL, wid, lane, apkH, apkL);
    }
    __syncthreads();

    for (int ci = 0; ci < NCHUNK; ++ci) {
        const bool more = (ci + 1 < NCHUNK);
        // ---- prefetch next chunk: B -> other smem buffer, A -> regs
        if (more) {
            const uint4* src = (const uint4*)(gB + (size_t)(ci + 1) * CHUNK_WORDS);
            uint4* dst = (uint4*)(sB0 + ((ci + 1) & 1) * CHUNK_WORDS);
            for (int i2 = tid; i2 < CHUNK_WORDS / 4; i2 += 256) dst[i2] = __ldg(src + i2);
            produce_chunk<CIN, STRIDE_IN>(fcat, s_nbr, s_w, wid, lane,
                                          (ci + 1) * 8, apkH, apkL);
        }

        // ---- MMA on current chunk
        const uint32_t* sB = sB0 + (ci & 1) * CHUNK_WORDS;
#pragma unroll
        for (int s = 0; s < 4; ++s) {
            const int off = s * 8 + 2 * t;
            uint2 ah0 = *(const uint2*)(sAH + (rowA)      * ROWW + off);
            uint2 ah1 = *(const uint2*)(sAH + (rowA + 8)  * ROWW + off);
            uint2 ah2 = *(const uint2*)(sAH + (rowA + 16) * ROWW + off);
            uint2 ah3 = *(const uint2*)(sAH + (rowA + 24) * ROWW + off);
            uint2 al0 = *(const uint2*)(sAL + (rowA)      * ROWW + off);
            uint2 al1 = *(const uint2*)(sAL + (rowA + 8)  * ROWW + off);
            uint2 al2 = *(const uint2*)(sAL + (rowA + 16) * ROWW + off);
            uint2 al3 = *(const uint2*)(sAL + (rowA + 24) * ROWW + off);
#pragma unroll
            for (int nt = 0; nt < 8; ++nt) {
                const int brow = ch * 64 + nt * 8 + g;
                uint2 bh = *(const uint2*)(sB + brow * ROWW + off);
                uint2 bl = *(const uint2*)(sB + 5120 + brow * ROWW + off);
                float* C0 = acc + nt * 4;
                float* C1 = acc + 32 + nt * 4;
                mma_bf16(C0, ah0.x, ah1.x, ah0.y, ah1.y, bh.x, bh.y);
                mma_bf16(C0, ah0.x, ah1.x, ah0.y, ah1.y, bl.x, bl.y);
                mma_bf16(C0, al0.x, al1.x, al0.y, al1.y, bh.x, bh.y);
                mma_bf16(C1, ah2.x, ah3.x, ah2.y, ah3.y, bh.x, bh.y);
                mma_bf16(C1, ah2.x, ah3.x, ah2.y, ah3.y, bl.x, bl.y);
                mma_bf16(C1, al2.x, al3.x, al2.y, al3.y, bh.x, bh.y);
            }
        }
        __syncthreads();
        if (more) store_chunkA(sAH, sAL, wid, lane, apkH, apkL);
        __syncthreads();
    }

    // ---- epilogue: bias + leaky
#pragma unroll
    for (int tile = 0; tile < 2; ++tile) {
        const int r0 = base + rt * 32 + tile * 16 + g;
#pragma unroll
        for (int nt = 0; nt < 8; ++nt) {
            const int col = ch * 64 + nt * 8 + 2 * t;
            float b0 = s_bias[col], b1 = s_bias[col + 1];
            const float* C = acc + tile * 32 + nt * 4;
            float2 r01 = make_float2(lrelu(C[0] + b0), lrelu(C[1] + b1));
            float2 r23 = make_float2(lrelu(C[2] + b0), lrelu(C[3] + b1));
            *(float2*)(out + (size_t)r0 * OUT_STRIDE + col) = r01;
            *(float2*)(out + (size_t)(r0 + 8) * OUT_STRIDE + col) = r23;
        }
    }
}

// ---------------- MLP head ------------------------------------------------------
__global__ void mlp_kernel(const float* __restrict__ w_last, const float* __restrict__ b1,
                           const float* __restrict__ b2, const float* __restrict__ blast,
                           float* __restrict__ out) {
    __shared__ float s_f[16 * 128];
    __shared__ float s_h1[16 * 128];
    __shared__ float s_h2[16 * 64];
    const int tid = threadIdx.x;
    const int p0  = blockIdx.x * 16;

    for (int i = tid; i < 16 * 128; i += 256) s_f[i] = g_f2[(size_t)p0 * 128 + i];
    __syncthreads();
    {
        int o = tid & 127, tg = tid >> 7;
        float acc[8];
#pragma unroll
        for (int i = 0; i < 8; ++i) acc[i] = 0.f;
        for (int c = 0; c < 128; ++c) {
            float wv = g_w1t[c * 128 + o];
#pragma unroll
            for (int i = 0; i < 8; ++i) acc[i] += s_f[(tg * 8 + i) * 128 + c] * wv;
        }
        float bb = b1[o];
#pragma unroll
        for (int i = 0; i < 8; ++i) s_h1[(tg * 8 + i) * 128 + o] = lrelu(acc[i] + bb);
    }
    __syncthreads();
    {
        int jj = tid & 63, tg = tid >> 6;
        float acc[4];
#pragma unroll
        for (int i = 0; i < 4; ++i) acc[i] = 0.f;
        for (int c = 0; c < 128; ++c) {
            float wv = g_w2t[c * 64 + jj];
#pragma unroll
            for (int i = 0; i < 4; ++i) acc[i] += s_h1[(tg * 4 + i) * 128 + c] * wv;
        }
        float bb = b2[jj];
#pragma unroll
        for (int i = 0; i < 4; ++i) s_h2[(tg * 4 + i) * 64 + jj] = lrelu(acc[i] + bb);
    }
    __syncthreads();

    const int b = p0 >> 13, n0 = p0 & (NPTS - 1);
    for (int i = tid; i < 16 * 64; i += 256) {
        int t2 = i & 15, jj = i >> 4;
        out[((size_t)(b * 64 + jj)) * NPTS + n0 + t2] = s_h2[t2 * 64 + jj];
    }
    if (tid < 48) {
        int t2 = tid & 15, d = tid >> 4;
        float acc = 0.f;
#pragma unroll 8
        for (int jj = 0; jj < 64; ++jj) acc += w_last[d * 64 + jj] * s_h2[t2 * 64 + jj];
        out[(size_t)BATCH * 64 * NPTS + ((size_t)(b * 3 + d)) * NPTS + n0 + t2] = acc + blast[d];
    }
}

// ---------------- launch ----------------------------------------------------------
extern "C" void kernel_launch(void* const* d_in, const int* in_sizes, int n_in,
                              void* d_out, int out_size) {
    const float* xyz    = (const float*)d_in[0];
    const float* feat   = (const float*)d_in[1];
    const int*   knn    = (const int*)d_in[2];
    const float* w_wn1  = (const float*)d_in[3];
    const float* b_wn1  = (const float*)d_in[4];
    const float* w_lin1 = (const float*)d_in[5];
    const float* b_lin1 = (const float*)d_in[6];
    const float* w_wn2  = (const float*)d_in[7];
    const float* b_wn2  = (const float*)d_in[8];
    const float* w_lin2 = (const float*)d_in[9];
    const float* b_lin2 = (const float*)d_in[10];
    const float* w_mlp1 = (const float*)d_in[11];
    const float* b_mlp1 = (const float*)d_in[12];
    const float* w_mlp2 = (const float*)d_in[13];
    const float* b_mlp2 = (const float*)d_in[14];
    const float* w_last = (const float*)d_in[15];
    const float* b_last = (const float*)d_in[16];
    float* out = (float*)d_out;

    void *p_fcat1, *p_fcat2, *p_f2, *p_B1, *p_B2;
    cudaGetSymbolAddress(&p_fcat1, g_fcat1);
    cudaGetSymbolAddress(&p_fcat2, g_fcat2);
    cudaGetSymbolAddress(&p_f2, g_f2);
    cudaGetSymbolAddress(&p_B1, g_B1);
    cudaGetSymbolAddress(&p_B2, g_B2);

    prep_weights<<<(128 * 128 + 255) / 256, 256>>>(w_mlp1, w_mlp2);
    prep_xyz<<<(NP_TOTAL * 3 + 255) / 256, 256>>>(xyz);
    prep_B<<<(NCH1 * CHUNK_WORDS + 255) / 256, 256>>>(w_lin1, w_lin2);
    {
        dim3 tb(32, 32);
        dim3 tg(NPTS / 32, 256 / 32, BATCH);
        transpose_feat<<<tg, tb>>>(feat);
    }

    cudaFuncSetAttribute(conv_mma<256, 260, 132, NCH1>,
                         cudaFuncAttributeMaxDynamicSharedMemorySize, DYN_BYTES);
    conv_mma<256, 260, 132, NCH1><<<NP_TOTAL / 128, 256, DYN_BYTES>>>(
        (const float*)p_fcat1, knn, w_wn1, b_wn1, b_lin1, (const uint32_t*)p_B1,
        (float*)p_fcat2);

    cudaFuncSetAttribute(conv_mma<128, 132, 128, NCH2>,
                         cudaFuncAttributeMaxDynamicSharedMemorySize, DYN_BYTES);
    conv_mma<128, 132, 128, NCH2><<<NP_TOTAL / 128, 256, DYN_BYTES>>>(
        (const float*)p_fcat2, knn, w_wn2, b_wn2, b_lin2, (const uint32_t*)p_B2,
        (float*)p_f2);

    mlp_kernel<<<NP_TOTAL / 16, 256>>>(w_last, b_mlp1, b_mlp2, b_last, out);
}

// round 7
// speedup vs baseline: 1.0699x; 1.0699x over previous
#include <cuda_runtime.h>
#include <cuda_bf16.h>
#include <cstdint>

#define BATCH 4
#define NPTS 8192
#define KNN 16
#define NP_TOTAL (BATCH * NPTS)

typedef unsigned long long ull;

#define NCH1 33   // conv1: 259 ch -> 33 chunks of 8 ch (64 f)
#define NCH2 17   // conv2: 131 ch -> 17 chunks
#define ROWW 40   // A/B row stride in words (80 bf16 = 160B)
#define WSTR 132  // s_w row stride in floats (pad kills pt-stride conflicts)
#define CHUNK_WORDS 10240   // per-chunk B image: 2 halves x 128 rows x 40 words

__device__ float g_fcat1[NP_TOTAL * 260];   // [p][256 feat | 3 xyz | pad]
__device__ float g_fcat2[NP_TOTAL * 132];   // [p][128 feat | 3 xyz | pad]
__device__ float g_f2[NP_TOTAL * 128];
__device__ uint32_t g_B1[NCH1 * CHUNK_WORDS];
__device__ uint32_t g_B2[NCH2 * CHUNK_WORDS];
__device__ float g_w1t[128 * 128];
__device__ float g_w2t[128 * 64];

__device__ __forceinline__ float lrelu(float v) { return v >= 0.f ? v : 0.1f * v; }
__device__ __forceinline__ ull ffma2(ull a, ull b, ull c) {
    ull d; asm("fma.rn.f32x2 %0, %1, %2, %3;" : "=l"(d) : "l"(a), "l"(b), "l"(c)); return d;
}
__device__ __forceinline__ ull dup2(float x) {
    ull d; asm("mov.b64 %0, {%1, %1};" : "=l"(d) : "f"(x)); return d;
}
__device__ __forceinline__ float2 unpk(ull v) {
    float2 r; asm("mov.b64 {%0, %1}, %2;" : "=f"(r.x), "=f"(r.y) : "l"(v)); return r;
}
__device__ __forceinline__ uint32_t pack_bf16(float a, float b) {
    __nv_bfloat162 h = __floats2bfloat162_rn(a, b);
    return *(uint32_t*)&h;
}
__device__ __forceinline__ float bf16r(float x) {
    return __bfloat162float(__float2bfloat16_rn(x));
}

__device__ __forceinline__ void mma_bf16(float* c, uint32_t a0, uint32_t a1,
                                         uint32_t a2, uint32_t a3,
                                         uint32_t b0, uint32_t b1) {
    asm volatile(
        "mma.sync.aligned.m16n8k16.row.col.f32.bf16.bf16.f32 "
        "{%0,%1,%2,%3}, {%4,%5,%6,%7}, {%8,%9}, {%0,%1,%2,%3};"
        : "+f"(c[0]), "+f"(c[1]), "+f"(c[2]), "+f"(c[3])
        : "r"(a0), "r"(a1), "r"(a2), "r"(a3), "r"(b0), "r"(b1));
}

// ---------------- prep ----------------------------------------------------------
__global__ void prep_weights(const float* __restrict__ wm1, const float* __restrict__ wm2) {
    int i = blockIdx.x * blockDim.x + threadIdx.x;
    if (i < 128 * 128) { int c = i >> 7, o = i & 127; g_w1t[i] = wm1[o * 128 + c]; }
    if (i < 128 * 64)  { int o = i >> 6, j = i & 63;  g_w2t[i] = wm2[j * 128 + o]; }
}

__global__ void prep_xyz(const float* __restrict__ xyz) {
    int i = blockIdx.x * blockDim.x + threadIdx.x;
    if (i >= NP_TOTAL * 3) return;
    int p = i / 3, d = i - p * 3;
    int b = p >> 13, n = p & (NPTS - 1);
    float v = xyz[((size_t)b * 3 + d) * NPTS + n];
    g_fcat1[(size_t)p * 260 + 256 + d] = v;
    g_fcat2[(size_t)p * 132 + 128 + d] = v;
    if (d == 0) {                      // zero pad words (read by float4 gathers)
        g_fcat1[(size_t)p * 260 + 259] = 0.f;
        g_fcat2[(size_t)p * 132 + 131] = 0.f;
    }
}

__global__ void transpose_feat(const float* __restrict__ feat) {
    __shared__ float tile[32][33];
    int b = blockIdx.z;
    int n0 = blockIdx.x * 32, c0 = blockIdx.y * 32;
    int x = threadIdx.x, y = threadIdx.y;
    tile[y][x] = feat[((size_t)b * 256 + c0 + y) * NPTS + n0 + x];
    __syncthreads();
    g_fcat1[((size_t)(b * NPTS + n0 + y)) * 260 + c0 + x] = tile[x][y];
}

// col layout per k16 sub: pos(k) = (k&1) | (((k>>1)&3)<<2) | (((k>>3)&1)<<1)
__device__ __forceinline__ float fetch_w(const float* wl, int Freal, int CIN, int n,
                                         int ci, int col) {
    if (col >= 64) return 0.f;
    int s = col >> 4, pos = col & 15;
    int k = (pos & 1) | (((pos >> 2) & 3) << 1) | (((pos >> 1) & 1) << 3);
    int f = ci * 64 + s * 16 + k;
    int c = f >> 3, m = f & 7;
    if (c >= CIN + 3) return 0.f;
    int co = (c < CIN) ? c + 3 : c - CIN;
    return wl[n * Freal + co * 8 + m];
}

__global__ void prep_B(const float* __restrict__ wl1, const float* __restrict__ wl2) {
    int i = blockIdx.x * blockDim.x + threadIdx.x;
    if (i < NCH1 * CHUNK_WORDS) {
        int ci = i / CHUNK_WORDS, r = i % CHUNK_WORDS;
        int h = r / 5120, r2 = r % 5120;
        int n = r2 / ROWW, wc = r2 % ROWW;
        float v0 = fetch_w(wl1, 2072, 256, n, ci, 2 * wc);
        float v1 = fetch_w(wl1, 2072, 256, n, ci, 2 * wc + 1);
        float h0 = bf16r(v0), h1 = bf16r(v1);
        g_B1[i] = h ? pack_bf16(v0 - h0, v1 - h1) : pack_bf16(h0, h1);
    }
    if (i < NCH2 * CHUNK_WORDS) {
        int ci = i / CHUNK_WORDS, r = i % CHUNK_WORDS;
        int h = r / 5120, r2 = r % 5120;
        int n = r2 / ROWW, wc = r2 % ROWW;
        float v0 = fetch_w(wl2, 1048, 128, n, ci, 2 * wc);
        float v1 = fetch_w(wl2, 1048, 128, n, ci, 2 * wc + 1);
        float h0 = bf16r(v0), h1 = bf16r(v1);
        g_B2[i] = h ? pack_bf16(v0 - h0, v1 - h1) : pack_bf16(h0, h1);
    }
}

// ---------------- fused point-conv (mma.sync bf16 3-term) ------------------------
// dyn smem word offsets:
#define OFF_A   0            // A image: hi 5120 | lo 5120
#define OFF_B   10240        // B double buffer: 2 x 10240
#define OFF_W   30720        // s_w fp32 [128][WSTR] = 16896
#define OFF_NBR 47616        // 2048 ints
#define OFF_CX  49664        // 384
#define OFF_BIAS 50048       // 128
#define DYN_WORDS 50176
#define DYN_BYTES (DYN_WORDS * 4)

template <int CIN, int STRIDE_IN, int OUT_STRIDE, int NCHUNK>
__global__ void __launch_bounds__(256, 1)
conv_mma(const float* __restrict__ fcat, const int* __restrict__ knn,
         const float* __restrict__ w_wn, const float* __restrict__ b_wn,
         const float* __restrict__ b_lin, const uint32_t* __restrict__ gB,
         float* __restrict__ out) {
    constexpr int CIN3 = CIN + 3;

    extern __shared__ float dyn[];
    uint32_t* sAH = (uint32_t*)dyn + OFF_A;
    uint32_t* sAL = sAH + 5120;
    uint32_t* sB0 = (uint32_t*)dyn + OFF_B;
    float* s_w    = dyn + OFF_W;
    int*   s_nbr  = (int*)(dyn + OFF_NBR);
    float* s_cx   = dyn + OFF_CX;
    float* s_bias = dyn + OFF_BIAS;

    __shared__ float s_wn[24];
    __shared__ float s_bwn[8];

    const int tid  = threadIdx.x;
    const int wid  = tid >> 5, lane = tid & 31;
    const int g    = lane >> 2, t = lane & 3;
    const int base = blockIdx.x * 128;
    const int boff = (base >> 13) << 13;

    if (tid < 24) s_wn[tid] = w_wn[tid];
    if (tid < 8)  s_bwn[tid] = b_wn[tid];
    if (tid < 128) {
        s_bias[tid] = b_lin[tid];
        const float* cp = fcat + (size_t)(base + tid) * STRIDE_IN + CIN;
        s_cx[tid * 3 + 0] = cp[0];
        s_cx[tid * 3 + 1] = cp[1];
        s_cx[tid * 3 + 2] = cp[2];
    }
#pragma unroll
    for (int r = 0; r < 8; ++r) {
        int id = tid + r * 256;
        int pt = id >> 4, k = id & 15;
        s_nbr[id] = boff + knn[(size_t)(base + pt) * KNN + k];
    }
    __syncthreads();

    // weight-net into s_w[pt][k*8+m], stride WSTR
#pragma unroll
    for (int r = 0; r < 8; ++r) {
        int id = tid + r * 256;
        int pt = id >> 4, k = id & 15;
        int j = s_nbr[id];
        const float* nx = fcat + (size_t)j * STRIDE_IN + CIN;
        float px = nx[0] - s_cx[pt * 3 + 0];
        float py = nx[1] - s_cx[pt * 3 + 1];
        float pz = nx[2] - s_cx[pt * 3 + 2];
#pragma unroll
        for (int m = 0; m < 8; ++m) {
            float v = s_wn[m * 3 + 0] * px + s_wn[m * 3 + 1] * py +
                      s_wn[m * 3 + 2] * pz + s_bwn[m];
            s_w[pt * WSTR + k * 8 + m] = lrelu(v);
        }
    }
    __syncthreads();

    // producer identity: lane = (ptl, quad); neighbor indices held in registers
    const int ptl  = lane >> 1;
    const int pt_p = wid * 16 + ptl;
    const int quad = lane & 1;
    int nb[16];
    {
        const int4* q = (const int4*)(s_nbr + pt_p * 16);
        int4 n0 = q[0], n1 = q[1], n2 = q[2], n3 = q[3];
        nb[0]=n0.x; nb[1]=n0.y; nb[2]=n0.z; nb[3]=n0.w;
        nb[4]=n1.x; nb[5]=n1.y; nb[6]=n1.z; nb[7]=n1.w;
        nb[8]=n2.x; nb[9]=n2.y; nb[10]=n2.z; nb[11]=n2.w;
        nb[12]=n3.x; nb[13]=n3.y; nb[14]=n3.z; nb[15]=n3.w;
    }
    const float* wp_p = s_w + pt_p * WSTR;
    uint4* dH = (uint4*)(sAH + pt_p * ROWW + quad * 16);
    uint4* dL = (uint4*)(sAL + pt_p * ROWW + quad * 16);

    float acc[64];
#pragma unroll
    for (int i = 0; i < 64; ++i) acc[i] = 0.f;

    // MMA warp tile: rows rt*32..+31, cols ch*64..+63
    const int rt = wid & 3, ch = wid >> 2;
    const int rowA = rt * 32 + g;

    // ---- produce A for chunk ci into smem (direct)
    auto produceA = [&](int ci) {
        const int cbase = ci * 8 + quad * 4;
        ull pa[16];
#pragma unroll
        for (int i = 0; i < 16; ++i) pa[i] = 0ULL;
        if (cbase < CIN3) {
            const float* fp = fcat + cbase;
#pragma unroll
            for (int k = 0; k < 16; ++k) {
                float4 f4 = __ldg((const float4*)(fp + (size_t)nb[k] * STRIDE_IN));
                ulonglong2 w01 = *(const ulonglong2*)(wp_p + k * 8);
                ulonglong2 w23 = *(const ulonglong2*)(wp_p + k * 8 + 4);
                ull f0 = dup2(f4.x), f1 = dup2(f4.y), f2 = dup2(f4.z), f3 = dup2(f4.w);
                pa[0]  = ffma2(f0, w01.x, pa[0]);
                pa[1]  = ffma2(f0, w01.y, pa[1]);
                pa[2]  = ffma2(f0, w23.x, pa[2]);
                pa[3]  = ffma2(f0, w23.y, pa[3]);
                pa[4]  = ffma2(f1, w01.x, pa[4]);
                pa[5]  = ffma2(f1, w01.y, pa[5]);
                pa[6]  = ffma2(f1, w23.x, pa[6]);
                pa[7]  = ffma2(f1, w23.y, pa[7]);
                pa[8]  = ffma2(f2, w01.x, pa[8]);
                pa[9]  = ffma2(f2, w01.y, pa[9]);
                pa[10] = ffma2(f2, w23.x, pa[10]);
                pa[11] = ffma2(f2, w23.y, pa[11]);
                pa[12] = ffma2(f3, w01.x, pa[12]);
                pa[13] = ffma2(f3, w01.y, pa[13]);
                pa[14] = ffma2(f3, w23.x, pa[14]);
                pa[15] = ffma2(f3, w23.y, pa[15]);
            }
        }
        uint32_t hiw[16], low[16];
#pragma unroll
        for (int g2 = 0; g2 < 2; ++g2) {
#pragma unroll
            for (int mp = 0; mp < 4; ++mp) {
                float2 va = unpk(pa[g2 * 8 + mp]);          // c even of pair
                float2 vb = unpk(pa[g2 * 8 + 4 + mp]);      // c odd of pair
                float ha0 = bf16r(va.x), ha1 = bf16r(va.y);
                float hb0 = bf16r(vb.x), hb1 = bf16r(vb.y);
                hiw[g2 * 8 + mp * 2 + 0] = pack_bf16(ha0, ha1);
                hiw[g2 * 8 + mp * 2 + 1] = pack_bf16(hb0, hb1);
                low[g2 * 8 + mp * 2 + 0] = pack_bf16(va.x - ha0, va.y - ha1);
                low[g2 * 8 + mp * 2 + 1] = pack_bf16(vb.x - hb0, vb.y - hb1);
            }
        }
        dH[0] = ((uint4*)hiw)[0]; dH[1] = ((uint4*)hiw)[1];
        dH[2] = ((uint4*)hiw)[2]; dH[3] = ((uint4*)hiw)[3];
        dL[0] = ((uint4*)low)[0]; dL[1] = ((uint4*)low)[1];
        dL[2] = ((uint4*)low)[2]; dL[3] = ((uint4*)low)[3];
    };

    // ---- prologue: B(0) copy + A(0) produce
    {
        const uint4* src = (const uint4*)(gB);
        uint4* dst = (uint4*)sB0;
        for (int i2 = tid; i2 < CHUNK_WORDS / 4; i2 += 256) dst[i2] = __ldg(src + i2);
        produceA(0);
    }
    __syncthreads();

    for (int ci = 0; ci < NCHUNK; ++ci) {
        const bool more = (ci + 1 < NCHUNK);
        // prefetch next B into alternate buffer (overlaps MMA below)
        if (more) {
            const uint4* src = (const uint4*)(gB + (size_t)(ci + 1) * CHUNK_WORDS);
            uint4* dst = (uint4*)(sB0 + ((ci + 1) & 1) * CHUNK_WORDS);
            for (int i2 = tid; i2 < CHUNK_WORDS / 4; i2 += 256) dst[i2] = __ldg(src + i2);
        }

        // MMA on current chunk
        const uint32_t* sB = sB0 + (ci & 1) * CHUNK_WORDS;
#pragma unroll
        for (int s = 0; s < 4; ++s) {
            const int off = s * 8 + 2 * t;
            uint2 ah0 = *(const uint2*)(sAH + (rowA)      * ROWW + off);
            uint2 ah1 = *(const uint2*)(sAH + (rowA + 8)  * ROWW + off);
            uint2 ah2 = *(const uint2*)(sAH + (rowA + 16) * ROWW + off);
            uint2 ah3 = *(const uint2*)(sAH + (rowA + 24) * ROWW + off);
            uint2 al0 = *(const uint2*)(sAL + (rowA)      * ROWW + off);
            uint2 al1 = *(const uint2*)(sAL + (rowA + 8)  * ROWW + off);
            uint2 al2 = *(const uint2*)(sAL + (rowA + 16) * ROWW + off);
            uint2 al3 = *(const uint2*)(sAL + (rowA + 24) * ROWW + off);
#pragma unroll
            for (int nt = 0; nt < 8; ++nt) {
                const int brow = ch * 64 + nt * 8 + g;
                uint2 bh = *(const uint2*)(sB + brow * ROWW + off);
                uint2 bl = *(const uint2*)(sB + 5120 + brow * ROWW + off);
                float* C0 = acc + nt * 4;
                float* C1 = acc + 32 + nt * 4;
                mma_bf16(C0, ah0.x, ah1.x, ah0.y, ah1.y, bh.x, bh.y);
                mma_bf16(C0, ah0.x, ah1.x, ah0.y, ah1.y, bl.x, bl.y);
                mma_bf16(C0, al0.x, al1.x, al0.y, al1.y, bh.x, bh.y);
                mma_bf16(C1, ah2.x, ah3.x, ah2.y, ah3.y, bh.x, bh.y);
                mma_bf16(C1, ah2.x, ah3.x, ah2.y, ah3.y, bl.x, bl.y);
                mma_bf16(C1, al2.x, al3.x, al2.y, al3.y, bh.x, bh.y);
            }
        }
        __syncthreads();                 // A reads complete
        if (more) produceA(ci + 1);      // overwrite A in place
        __syncthreads();                 // A writes + B prefetch visible
    }

    // ---- epilogue: bias + leaky
#pragma unroll
    for (int tile = 0; tile < 2; ++tile) {
        const int r0 = base + rt * 32 + tile * 16 + g;
#pragma unroll
        for (int nt = 0; nt < 8; ++nt) {
            const int col = ch * 64 + nt * 8 + 2 * t;
            float b0 = s_bias[col], b1 = s_bias[col + 1];
            const float* C = acc + tile * 32 + nt * 4;
            float2 r01 = make_float2(lrelu(C[0] + b0), lrelu(C[1] + b1));
            float2 r23 = make_float2(lrelu(C[2] + b0), lrelu(C[3] + b1));
            *(float2*)(out + (size_t)r0 * OUT_STRIDE + col) = r01;
            *(float2*)(out + (size_t)(r0 + 8) * OUT_STRIDE + col) = r23;
        }
    }
}

// ---------------- MLP head ------------------------------------------------------
__global__ void mlp_kernel(const float* __restrict__ w_last, const float* __restrict__ b1,
                           const float* __restrict__ b2, const float* __restrict__ blast,
                           float* __restrict__ out) {
    __shared__ float s_f[16 * 128];
    __shared__ float s_h1[16 * 128];
    __shared__ float s_h2[16 * 64];
    const int tid = threadIdx.x;
    const int p0  = blockIdx.x * 16;

    for (int i = tid; i < 16 * 128; i += 256) s_f[i] = g_f2[(size_t)p0 * 128 + i];
    __syncthreads();
    {
        int o = tid & 127, tg = tid >> 7;
        float acc[8];
#pragma unroll
        for (int i = 0; i < 8; ++i) acc[i] = 0.f;
        for (int c = 0; c < 128; ++c) {
            float wv = g_w1t[c * 128 + o];
#pragma unroll
            for (int i = 0; i < 8; ++i) acc[i] += s_f[(tg * 8 + i) * 128 + c] * wv;
        }
        float bb = b1[o];
#pragma unroll
        for (int i = 0; i < 8; ++i) s_h1[(tg * 8 + i) * 128 + o] = lrelu(acc[i] + bb);
    }
    __syncthreads();
    {
        int jj = tid & 63, tg = tid >> 6;
        float acc[4];
#pragma unroll
        for (int i = 0; i < 4; ++i) acc[i] = 0.f;
        for (int c = 0; c < 128; ++c) {
            float wv = g_w2t[c * 64 + jj];
#pragma unroll
            for (int i = 0; i < 4; ++i) acc[i] += s_h1[(tg * 4 + i) * 128 + c] * wv;
        }
        float bb = b2[jj];
#pragma unroll
        for (int i = 0; i < 4; ++i) s_h2[(tg * 4 + i) * 64 + jj] = lrelu(acc[i] + bb);
    }
    __syncthreads();

    const int b = p0 >> 13, n0 = p0 & (NPTS - 1);
    for (int i = tid; i < 16 * 64; i += 256) {
        int t2 = i & 15, jj = i >> 4;
        out[((size_t)(b * 64 + jj)) * NPTS + n0 + t2] = s_h2[t2 * 64 + jj];
    }
    if (tid < 48) {
        int t2 = tid & 15, d = tid >> 4;
        float acc = 0.f;
#pragma unroll 8
        for (int jj = 0; jj < 64; ++jj) acc += w_last[d * 64 + jj] * s_h2[t2 * 64 + jj];
        out[(size_t)BATCH * 64 * NPTS + ((size_t)(b * 3 + d)) * NPTS + n0 + t2] = acc + blast[d];
    }
}

// ---------------- launch ----------------------------------------------------------
extern "C" void kernel_launch(void* const* d_in, const int* in_sizes, int n_in,
                              void* d_out, int out_size) {
    const float* xyz    = (const float*)d_in[0];
    const float* feat   = (const float*)d_in[1];
    const int*   knn    = (const int*)d_in[2];
    const float* w_wn1  = (const float*)d_in[3];
    const float* b_wn1  = (const float*)d_in[4];
    const float* w_lin1 = (const float*)d_in[5];
    const float* b_lin1 = (const float*)d_in[6];
    const float* w_wn2  = (const float*)d_in[7];
    const float* b_wn2  = (const float*)d_in[8];
    const float* w_lin2 = (const float*)d_in[9];
    const float* b_lin2 = (const float*)d_in[10];
    const float* w_mlp1 = (const float*)d_in[11];
    const float* b_mlp1 = (const float*)d_in[12];
    const float* w_mlp2 = (const float*)d_in[13];
    const float* b_mlp2 = (const float*)d_in[14];
    const float* w_last = (const float*)d_in[15];
    const float* b_last = (const float*)d_in[16];
    float* out = (float*)d_out;

    void *p_fcat1, *p_fcat2, *p_f2, *p_B1, *p_B2;
    cudaGetSymbolAddress(&p_fcat1, g_fcat1);
    cudaGetSymbolAddress(&p_fcat2, g_fcat2);
    cudaGetSymbolAddress(&p_f2, g_f2);
    cudaGetSymbolAddress(&p_B1, g_B1);
    cudaGetSymbolAddress(&p_B2, g_B2);

    prep_weights<<<(128 * 128 + 255) / 256, 256>>>(w_mlp1, w_mlp2);
    prep_xyz<<<(NP_TOTAL * 3 + 255) / 256, 256>>>(xyz);
    prep_B<<<(NCH1 * CHUNK_WORDS + 255) / 256, 256>>>(w_lin1, w_lin2);
    {
        dim3 tb(32, 32);
        dim3 tg(NPTS / 32, 256 / 32, BATCH);
        transpose_feat<<<tg, tb>>>(feat);
    }

    cudaFuncSetAttribute(conv_mma<256, 260, 132, NCH1>,
                         cudaFuncAttributeMaxDynamicSharedMemorySize, DYN_BYTES);
    conv_mma<256, 260, 132, NCH1><<<NP_TOTAL / 128, 256, DYN_BYTES>>>(
        (const float*)p_fcat1, knn, w_wn1, b_wn1, b_lin1, (const uint32_t*)p_B1,
        (float*)p_fcat2);

    cudaFuncSetAttribute(conv_mma<128, 132, 128, NCH2>,
                         cudaFuncAttributeMaxDynamicSharedMemorySize, DYN_BYTES);
    conv_mma<128, 132, 128, NCH2><<<NP_TOTAL / 128, 256, DYN_BYTES>>>(
        (const float*)p_fcat2, knn, w_wn2, b_wn2, b_lin2, (const uint32_t*)p_B2,
        (float*)p_f2);

    mlp_kernel<<<NP_TOTAL / 16, 256>>>(w_last, b_mlp1, b_mlp2, b_last, out);
}

// round 8
// speedup vs baseline: 1.3126x; 1.2268x over previous
#include <cuda_runtime.h>
#include <cuda_bf16.h>
#include <cstdint>

#define BATCH 4
#define NPTS 8192
#define KNN 16
#define NP_TOTAL (BATCH * NPTS)

typedef unsigned long long ull;

#define NCH1 33   // conv1: 259 ch -> 33 chunks of 8 ch (64 f)
#define NCH2 17   // conv2: 131 ch -> 17 chunks
#define ROWW 40   // A/B row stride in words (80 bf16 = 160B)
#define WSTR 132  // s_w row stride in floats
#define CHUNK_WORDS 10240   // per-chunk image: 2 halves x 128 rows x 40 words
#define NGROUPS (NP_TOTAL / 128)   // 256

__device__ float g_fcat1[NP_TOTAL * 260];   // [p][256 feat | 3 xyz | pad]
__device__ float g_fcat2[NP_TOTAL * 132];   // [p][128 feat | 3 xyz | pad]
__device__ float g_f2[NP_TOTAL * 128];
__device__ uint32_t g_B1[NCH1 * CHUNK_WORDS];
__device__ uint32_t g_B2[NCH2 * CHUNK_WORDS];
__device__ uint32_t g_A[(size_t)NGROUPS * NCH1 * CHUNK_WORDS];   // A scratch (reused)
__device__ float g_w1t[128 * 128];
__device__ float g_w2t[128 * 64];

__device__ __forceinline__ float lrelu(float v) { return v >= 0.f ? v : 0.1f * v; }
__device__ __forceinline__ ull ffma2(ull a, ull b, ull c) {
    ull d; asm("fma.rn.f32x2 %0, %1, %2, %3;" : "=l"(d) : "l"(a), "l"(b), "l"(c)); return d;
}
__device__ __forceinline__ ull dup2(float x) {
    ull d; asm("mov.b64 %0, {%1, %1};" : "=l"(d) : "f"(x)); return d;
}
__device__ __forceinline__ float2 unpk(ull v) {
    float2 r; asm("mov.b64 {%0, %1}, %2;" : "=f"(r.x), "=f"(r.y) : "l"(v)); return r;
}
__device__ __forceinline__ uint32_t pack_bf16(float a, float b) {
    __nv_bfloat162 h = __floats2bfloat162_rn(a, b);
    return *(uint32_t*)&h;
}
__device__ __forceinline__ float bf16r(float x) {
    return __bfloat162float(__float2bfloat16_rn(x));
}
__device__ __forceinline__ uint32_t s2u(const void* p) {
    uint32_t a;
    asm("{ .reg .u64 t; cvta.to.shared.u64 t, %1; cvt.u32.u64 %0, t; }" : "=r"(a) : "l"(p));
    return a;
}
__device__ __forceinline__ void cp16(uint32_t dst, const void* src) {
    asm volatile("cp.async.cg.shared.global [%0], [%1], 16;" :: "r"(dst), "l"(src));
}

__device__ __forceinline__ void mma_bf16(float* c, uint32_t a0, uint32_t a1,
                                         uint32_t a2, uint32_t a3,
                                         uint32_t b0, uint32_t b1) {
    asm volatile(
        "mma.sync.aligned.m16n8k16.row.col.f32.bf16.bf16.f32 "
        "{%0,%1,%2,%3}, {%4,%5,%6,%7}, {%8,%9}, {%0,%1,%2,%3};"
        : "+f"(c[0]), "+f"(c[1]), "+f"(c[2]), "+f"(c[3])
        : "r"(a0), "r"(a1), "r"(a2), "r"(a3), "r"(b0), "r"(b1));
}

// ---------------- transpose (launch #1) ------------------------------------------
__global__ void transpose_feat(const float* __restrict__ feat) {
    __shared__ float tile[32][33];
    int b = blockIdx.z;
    int n0 = blockIdx.x * 32, c0 = blockIdx.y * 32;
    int x = threadIdx.x, y = threadIdx.y;
    tile[y][x] = feat[((size_t)b * 256 + c0 + y) * NPTS + n0 + x];
    __syncthreads();
    g_fcat1[((size_t)(b * NPTS + n0 + y)) * 260 + c0 + x] = tile[x][y];
}

// col layout per k16 sub: pos(k) = (k&1) | (((k>>1)&3)<<2) | (((k>>3)&1)<<1)
__device__ __forceinline__ float fetch_w(const float* wl, int Freal, int CIN, int n,
                                         int ci, int col) {
    if (col >= 64) return 0.f;
    int s = col >> 4, pos = col & 15;
    int k = (pos & 1) | (((pos >> 2) & 3) << 1) | (((pos >> 1) & 1) << 3);
    int f = ci * 64 + s * 16 + k;
    int c = f >> 3, m = f & 7;
    if (c >= CIN + 3) return 0.f;
    int co = (c < CIN) ? c + 3 : c - CIN;
    return wl[n * Freal + co * 8 + m];
}

// ---------------- merged prep (launch #2) -----------------------------------------
__global__ void prep_all(const float* __restrict__ xyz,
                         const float* __restrict__ wl1, const float* __restrict__ wl2,
                         const float* __restrict__ wm1, const float* __restrict__ wm2) {
    int i = blockIdx.x * blockDim.x + threadIdx.x;
    if (i < 128 * 128) { int c = i >> 7, o = i & 127; g_w1t[i] = wm1[o * 128 + c]; }
    if (i < 128 * 64)  { int o = i >> 6, j = i & 63;  g_w2t[i] = wm2[j * 128 + o]; }
    if (i < NP_TOTAL * 3) {
        int p = i / 3, d = i - p * 3;
        int b = p >> 13, n = p & (NPTS - 1);
        float v = xyz[((size_t)b * 3 + d) * NPTS + n];
        g_fcat1[(size_t)p * 260 + 256 + d] = v;
        g_fcat2[(size_t)p * 132 + 128 + d] = v;
        if (d == 0) {
            g_fcat1[(size_t)p * 260 + 259] = 0.f;
            g_fcat2[(size_t)p * 132 + 131] = 0.f;
        }
    }
    if (i < NCH1 * CHUNK_WORDS) {
        int ci = i / CHUNK_WORDS, r = i % CHUNK_WORDS;
        int h = r / 5120, r2 = r % 5120;
        int n = r2 / ROWW, wc = r2 % ROWW;
        float v0 = fetch_w(wl1, 2072, 256, n, ci, 2 * wc);
        float v1 = fetch_w(wl1, 2072, 256, n, ci, 2 * wc + 1);
        float h0 = bf16r(v0), h1 = bf16r(v1);
        g_B1[i] = h ? pack_bf16(v0 - h0, v1 - h1) : pack_bf16(h0, h1);
    }
    if (i < NCH2 * CHUNK_WORDS) {
        int ci = i / CHUNK_WORDS, r = i % CHUNK_WORDS;
        int h = r / 5120, r2 = r % 5120;
        int n = r2 / ROWW, wc = r2 % ROWW;
        float v0 = fetch_w(wl2, 1048, 128, n, ci, 2 * wc);
        float v1 = fetch_w(wl2, 1048, 128, n, ci, 2 * wc + 1);
        float h0 = bf16r(v0), h1 = bf16r(v1);
        g_B2[i] = h ? pack_bf16(v0 - h0, v1 - h1) : pack_bf16(h0, h1);
    }
}

// ---------------- producer: gather + weight-net -> A images in gmem ---------------
// dyn smem words: s_w [128][WSTR]=16896 | nbr 2048 | cx 384 -> 19328 w = 77312 B
#define P_OFF_W   0
#define P_OFF_NBR 16896
#define P_OFF_CX  18944
#define P_DYN_BYTES (19328 * 4)

template <int CIN, int STRIDE_IN, int NCHUNK>
__global__ void __launch_bounds__(256, 2)
producer(const float* __restrict__ fcat, const int* __restrict__ knn,
         const float* __restrict__ w_wn, const float* __restrict__ b_wn,
         uint32_t* __restrict__ gA) {
    constexpr int CIN3 = CIN + 3;

    extern __shared__ float dyn[];
    float* s_w   = dyn + P_OFF_W;
    int*   s_nbr = (int*)(dyn + P_OFF_NBR);
    float* s_cx  = dyn + P_OFF_CX;

    __shared__ float s_wn[24];
    __shared__ float s_bwn[8];

    const int tid  = threadIdx.x;
    const int wid  = tid >> 5, lane = tid & 31;
    const int base = blockIdx.x * 128;
    const int boff = (base >> 13) << 13;

    if (tid < 24) s_wn[tid] = w_wn[tid];
    if (tid < 8)  s_bwn[tid] = b_wn[tid];
    if (tid < 128) {
        const float* cp = fcat + (size_t)(base + tid) * STRIDE_IN + CIN;
        s_cx[tid * 3 + 0] = cp[0];
        s_cx[tid * 3 + 1] = cp[1];
        s_cx[tid * 3 + 2] = cp[2];
    }
#pragma unroll
    for (int r = 0; r < 8; ++r) {
        int id = tid + r * 256;
        int pt = id >> 4, k = id & 15;
        s_nbr[id] = boff + knn[(size_t)(base + pt) * KNN + k];
    }
    __syncthreads();

#pragma unroll
    for (int r = 0; r < 8; ++r) {
        int id = tid + r * 256;
        int pt = id >> 4, k = id & 15;
        int j = s_nbr[id];
        const float* nx = fcat + (size_t)j * STRIDE_IN + CIN;
        float px = nx[0] - s_cx[pt * 3 + 0];
        float py = nx[1] - s_cx[pt * 3 + 1];
        float pz = nx[2] - s_cx[pt * 3 + 2];
#pragma unroll
        for (int m = 0; m < 8; ++m) {
            float v = s_wn[m * 3 + 0] * px + s_wn[m * 3 + 1] * py +
                      s_wn[m * 3 + 2] * pz + s_bwn[m];
            s_w[pt * WSTR + k * 8 + m] = lrelu(v);
        }
    }
    __syncthreads();

    const int ptl  = lane >> 1;
    const int pt_p = wid * 16 + ptl;
    const int quad = lane & 1;
    int nb[16];
    {
        const int4* q = (const int4*)(s_nbr + pt_p * 16);
        int4 n0 = q[0], n1 = q[1], n2 = q[2], n3 = q[3];
        nb[0]=n0.x; nb[1]=n0.y; nb[2]=n0.z; nb[3]=n0.w;
        nb[4]=n1.x; nb[5]=n1.y; nb[6]=n1.z; nb[7]=n1.w;
        nb[8]=n2.x; nb[9]=n2.y; nb[10]=n2.z; nb[11]=n2.w;
        nb[12]=n3.x; nb[13]=n3.y; nb[14]=n3.z; nb[15]=n3.w;
    }
    const float* wp_p = s_w + pt_p * WSTR;

    for (int ci = 0; ci < NCHUNK; ++ci) {
        const int cbase = ci * 8 + quad * 4;
        ull pa[16];
#pragma unroll
        for (int i = 0; i < 16; ++i) pa[i] = 0ULL;
        if (cbase < CIN3) {
            const float* fp = fcat + cbase;
#pragma unroll
            for (int k = 0; k < 16; ++k) {
                float4 f4 = __ldg((const float4*)(fp + (size_t)nb[k] * STRIDE_IN));
                ulonglong2 w01 = *(const ulonglong2*)(wp_p + k * 8);
                ulonglong2 w23 = *(const ulonglong2*)(wp_p + k * 8 + 4);
                ull f0 = dup2(f4.x), f1 = dup2(f4.y), f2 = dup2(f4.z), f3 = dup2(f4.w);
                pa[0]  = ffma2(f0, w01.x, pa[0]);
                pa[1]  = ffma2(f0, w01.y, pa[1]);
                pa[2]  = ffma2(f0, w23.x, pa[2]);
                pa[3]  = ffma2(f0, w23.y, pa[3]);
                pa[4]  = ffma2(f1, w01.x, pa[4]);
                pa[5]  = ffma2(f1, w01.y, pa[5]);
                pa[6]  = ffma2(f1, w23.x, pa[6]);
                pa[7]  = ffma2(f1, w23.y, pa[7]);
                pa[8]  = ffma2(f2, w01.x, pa[8]);
                pa[9]  = ffma2(f2, w01.y, pa[9]);
                pa[10] = ffma2(f2, w23.x, pa[10]);
                pa[11] = ffma2(f2, w23.y, pa[11]);
                pa[12] = ffma2(f3, w01.x, pa[12]);
                pa[13] = ffma2(f3, w01.y, pa[13]);
                pa[14] = ffma2(f3, w23.x, pa[14]);
                pa[15] = ffma2(f3, w23.y, pa[15]);
            }
        }
        uint32_t hiw[16], low[16];
#pragma unroll
        for (int g2 = 0; g2 < 2; ++g2) {
#pragma unroll
            for (int mp = 0; mp < 4; ++mp) {
                float2 va = unpk(pa[g2 * 8 + mp]);
                float2 vb = unpk(pa[g2 * 8 + 4 + mp]);
                float ha0 = bf16r(va.x), ha1 = bf16r(va.y);
                float hb0 = bf16r(vb.x), hb1 = bf16r(vb.y);
                hiw[g2 * 8 + mp * 2 + 0] = pack_bf16(ha0, ha1);
                hiw[g2 * 8 + mp * 2 + 1] = pack_bf16(hb0, hb1);
                low[g2 * 8 + mp * 2 + 0] = pack_bf16(va.x - ha0, va.y - ha1);
                low[g2 * 8 + mp * 2 + 1] = pack_bf16(vb.x - hb0, vb.y - hb1);
            }
        }
        uint32_t* outp = gA + ((size_t)blockIdx.x * NCHUNK + ci) * CHUNK_WORDS
                       + pt_p * ROWW + quad * 16;
        ((uint4*)outp)[0] = ((uint4*)hiw)[0];
        ((uint4*)outp)[1] = ((uint4*)hiw)[1];
        ((uint4*)outp)[2] = ((uint4*)hiw)[2];
        ((uint4*)outp)[3] = ((uint4*)hiw)[3];
        uint32_t* outl = outp + 5120;
        ((uint4*)outl)[0] = ((uint4*)low)[0];
        ((uint4*)outl)[1] = ((uint4*)low)[1];
        ((uint4*)outl)[2] = ((uint4*)low)[2];
        ((uint4*)outl)[3] = ((uint4*)low)[3];
    }
}

// ---------------- GEMM: cp.async pipelined bf16 3-term MMA -----------------------
// dyn smem words: A0 0 | A1 10240 | B0 20480 | B1 30720 | bias 40960 -> 41088 w
#define G_OFF_A0 0
#define G_OFF_A1 10240
#define G_OFF_B0 20480
#define G_OFF_B1 30720
#define G_OFF_BIAS 40960
#define G_DYN_BYTES (41088 * 4)

template <int OUT_STRIDE, int NCHUNK>
__global__ void __launch_bounds__(256, 1)
gemm_mma(const uint32_t* __restrict__ gA, const uint32_t* __restrict__ gB,
         const float* __restrict__ b_lin, float* __restrict__ out) {
    extern __shared__ float dyn[];
    uint32_t* smw = (uint32_t*)dyn;
    float* s_bias = dyn + G_OFF_BIAS;

    const int tid  = threadIdx.x;
    const int wid  = tid >> 5, lane = tid & 31;
    const int g    = lane >> 2, t = lane & 3;
    const int base = blockIdx.x * 128;

    if (tid < 128) s_bias[tid] = b_lin[tid];

    const uint32_t aBuf[2] = { s2u(smw + G_OFF_A0), s2u(smw + G_OFF_A1) };
    const uint32_t bBuf[2] = { s2u(smw + G_OFF_B0), s2u(smw + G_OFF_B1) };

    auto copy_chunk = [&](int ci) {
        const int bsel = ci & 1;
        const uint4* srcA = (const uint4*)(gA + ((size_t)blockIdx.x * NCHUNK + ci) * CHUNK_WORDS);
        const uint4* srcB = (const uint4*)(gB + (size_t)ci * CHUNK_WORDS);
        const uint32_t dA = aBuf[bsel], dB = bBuf[bsel];
#pragma unroll
        for (int r = 0; r < 10; ++r) {
            int i = tid + r * 256;
            cp16(dA + i * 16, srcA + i);
            cp16(dB + i * 16, srcB + i);
        }
        asm volatile("cp.async.commit_group;");
    };

    copy_chunk(0);

    float acc[64];
#pragma unroll
    for (int i = 0; i < 64; ++i) acc[i] = 0.f;

    const int rt = wid & 3, ch = wid >> 2;
    const int rowA = rt * 32 + g;

    for (int ci = 0; ci < NCHUNK; ++ci) {
        const bool more = (ci + 1 < NCHUNK);
        if (more) {
            copy_chunk(ci + 1);
            asm volatile("cp.async.wait_group 1;");
        } else {
            asm volatile("cp.async.wait_group 0;");
        }
        __syncthreads();

        const uint32_t* sAH = smw + ((ci & 1) ? G_OFF_A1 : G_OFF_A0);
        const uint32_t* sAL = sAH + 5120;
        const uint32_t* sB  = smw + ((ci & 1) ? G_OFF_B1 : G_OFF_B0);
#pragma unroll
        for (int s = 0; s < 4; ++s) {
            const int off = s * 8 + 2 * t;
            uint2 ah0 = *(const uint2*)(sAH + (rowA)      * ROWW + off);
            uint2 ah1 = *(const uint2*)(sAH + (rowA + 8)  * ROWW + off);
            uint2 ah2 = *(const uint2*)(sAH + (rowA + 16) * ROWW + off);
            uint2 ah3 = *(const uint2*)(sAH + (rowA + 24) * ROWW + off);
            uint2 al0 = *(const uint2*)(sAL + (rowA)      * ROWW + off);
            uint2 al1 = *(const uint2*)(sAL + (rowA + 8)  * ROWW + off);
            uint2 al2 = *(const uint2*)(sAL + (rowA + 16) * ROWW + off);
            uint2 al3 = *(const uint2*)(sAL + (rowA + 24) * ROWW + off);
#pragma unroll
            for (int nt = 0; nt < 8; ++nt) {
                const int brow = ch * 64 + nt * 8 + g;
                uint2 bh = *(const uint2*)(sB + brow * ROWW + off);
                uint2 bl = *(const uint2*)(sB + 5120 + brow * ROWW + off);
                float* C0 = acc + nt * 4;
                float* C1 = acc + 32 + nt * 4;
                mma_bf16(C0, ah0.x, ah1.x, ah0.y, ah1.y, bh.x, bh.y);
                mma_bf16(C0, ah0.x, ah1.x, ah0.y, ah1.y, bl.x, bl.y);
                mma_bf16(C0, al0.x, al1.x, al0.y, al1.y, bh.x, bh.y);
                mma_bf16(C1, ah2.x, ah3.x, ah2.y, ah3.y, bh.x, bh.y);
                mma_bf16(C1, ah2.x, ah3.x, ah2.y, ah3.y, bl.x, bl.y);
                mma_bf16(C1, al2.x, al3.x, al2.y, al3.y, bh.x, bh.y);
            }
        }
        __syncthreads();
    }

#pragma unroll
    for (int tile = 0; tile < 2; ++tile) {
        const int r0 = base + rt * 32 + tile * 16 + g;
#pragma unroll
        for (int nt = 0; nt < 8; ++nt) {
            const int col = ch * 64 + nt * 8 + 2 * t;
            float b0 = s_bias[col], b1 = s_bias[col + 1];
            const float* C = acc + tile * 32 + nt * 4;
            float2 r01 = make_float2(lrelu(C[0] + b0), lrelu(C[1] + b1));
            float2 r23 = make_float2(lrelu(C[2] + b0), lrelu(C[3] + b1));
            *(float2*)(out + (size_t)r0 * OUT_STRIDE + col) = r01;
            *(float2*)(out + (size_t)(r0 + 8) * OUT_STRIDE + col) = r23;
        }
    }
}

// ---------------- MLP head --------------------------------------------------------
__global__ void mlp_kernel(const float* __restrict__ w_last, const float* __restrict__ b1,
                           const float* __restrict__ b2, const float* __restrict__ blast,
                           float* __restrict__ out) {
    __shared__ float s_f[16 * 128];
    __shared__ float s_h1[16 * 128];
    __shared__ float s_h2[16 * 64];
    const int tid = threadIdx.x;
    const int p0  = blockIdx.x * 16;

    for (int i = tid; i < 16 * 128; i += 256) s_f[i] = g_f2[(size_t)p0 * 128 + i];
    __syncthreads();
    {
        int o = tid & 127, tg = tid >> 7;
        float acc[8];
#pragma unroll
        for (int i = 0; i < 8; ++i) acc[i] = 0.f;
        for (int c = 0; c < 128; ++c) {
            float wv = g_w1t[c * 128 + o];
#pragma unroll
            for (int i = 0; i < 8; ++i) acc[i] += s_f[(tg * 8 + i) * 128 + c] * wv;
        }
        float bb = b1[o];
#pragma unroll
        for (int i = 0; i < 8; ++i) s_h1[(tg * 8 + i) * 128 + o] = lrelu(acc[i] + bb);
    }
    __syncthreads();
    {
        int jj = tid & 63, tg = tid >> 6;
        float acc[4];
#pragma unroll
        for (int i = 0; i < 4; ++i) acc[i] = 0.f;
        for (int c = 0; c < 128; ++c) {
            float wv = g_w2t[c * 64 + jj];
#pragma unroll
            for (int i = 0; i < 4; ++i) acc[i] += s_h1[(tg * 4 + i) * 128 + c] * wv;
        }
        float bb = b2[jj];
#pragma unroll
        for (int i = 0; i < 4; ++i) s_h2[(tg * 4 + i) * 64 + jj] = lrelu(acc[i] + bb);
    }
    __syncthreads();

    const int b = p0 >> 13, n0 = p0 & (NPTS - 1);
    for (int i = tid; i < 16 * 64; i += 256) {
        int t2 = i & 15, jj = i >> 4;
        out[((size_t)(b * 64 + jj)) * NPTS + n0 + t2] = s_h2[t2 * 64 + jj];
    }
    if (tid < 48) {
        int t2 = tid & 15, d = tid >> 4;
        float acc = 0.f;
#pragma unroll 8
        for (int jj = 0; jj < 64; ++jj) acc += w_last[d * 64 + jj] * s_h2[t2 * 64 + jj];
        out[(size_t)BATCH * 64 * NPTS + ((size_t)(b * 3 + d)) * NPTS + n0 + t2] = acc + blast[d];
    }
}

// ---------------- launch ------------------------------------------------------------
extern "C" void kernel_launch(void* const* d_in, const int* in_sizes, int n_in,
                              void* d_out, int out_size) {
    const float* xyz    = (const float*)d_in[0];
    const float* feat   = (const float*)d_in[1];
    const int*   knn    = (const int*)d_in[2];
    const float* w_wn1  = (const float*)d_in[3];
    const float* b_wn1  = (const float*)d_in[4];
    const float* w_lin1 = (const float*)d_in[5];
    const float* b_lin1 = (const float*)d_in[6];
    const float* w_wn2  = (const float*)d_in[7];
    const float* b_wn2  = (const float*)d_in[8];
    const float* w_lin2 = (const float*)d_in[9];
    const float* b_lin2 = (const float*)d_in[10];
    const float* w_mlp1 = (const float*)d_in[11];
    const float* b_mlp1 = (const float*)d_in[12];
    const float* w_mlp2 = (const float*)d_in[13];
    const float* b_mlp2 = (const float*)d_in[14];
    const float* w_last = (const float*)d_in[15];
    const float* b_last = (const float*)d_in[16];
    float* out = (float*)d_out;

    void *p_fcat1, *p_fcat2, *p_f2, *p_B1, *p_B2, *p_A;
    cudaGetSymbolAddress(&p_fcat1, g_fcat1);
    cudaGetSymbolAddress(&p_fcat2, g_fcat2);
    cudaGetSymbolAddress(&p_f2, g_f2);
    cudaGetSymbolAddress(&p_B1, g_B1);
    cudaGetSymbolAddress(&p_B2, g_B2);
    cudaGetSymbolAddress(&p_A, g_A);

    // #1 transpose, #2 prep_all, #3 P1, #4 G1 (ncu capture slot), #5 P2, #6 G2, #7 mlp
    {
        dim3 tb(32, 32);
        dim3 tg(NPTS / 32, 256 / 32, BATCH);
        transpose_feat<<<tg, tb>>>(feat);
    }
    prep_all<<<(NCH1 * CHUNK_WORDS + 255) / 256, 256>>>(xyz, w_lin1, w_lin2, w_mlp1, w_mlp2);

    cudaFuncSetAttribute(producer<256, 260, NCH1>,
                         cudaFuncAttributeMaxDynamicSharedMemorySize, P_DYN_BYTES);
    producer<256, 260, NCH1><<<NGROUPS, 256, P_DYN_BYTES>>>(
        (const float*)p_fcat1, knn, w_wn1, b_wn1, (uint32_t*)p_A);

    cudaFuncSetAttribute(gemm_mma<132, NCH1>,
                         cudaFuncAttributeMaxDynamicSharedMemorySize, G_DYN_BYTES);
    gemm_mma<132, NCH1><<<NGROUPS, 256, G_DYN_BYTES>>>(
        (const uint32_t*)p_A, (const uint32_t*)p_B1, b_lin1, (float*)p_fcat2);

    cudaFuncSetAttribute(producer<128, 132, NCH2>,
                         cudaFuncAttributeMaxDynamicSharedMemorySize, P_DYN_BYTES);
    producer<128, 132, NCH2><<<NGROUPS, 256, P_DYN_BYTES>>>(
        (const float*)p_fcat2, knn, w_wn2, b_wn2, (uint32_t*)p_A);

    cudaFuncSetAttribute(gemm_mma<128, NCH2>,
                         cudaFuncAttributeMaxDynamicSharedMemorySize, G_DYN_BYTES);
    gemm_mma<128, NCH2><<<NGROUPS, 256, G_DYN_BYTES>>>(
        (const uint32_t*)p_A, (const uint32_t*)p_B2, b_lin2, (float*)p_f2);

    mlp_kernel<<<NP_TOTAL / 16, 256>>>(w_last, b_mlp1, b_mlp2, b_last, out);
}

// round 9
// speedup vs baseline: 1.3127x; 1.0000x over previous
#include <cuda_runtime.h>
#include <cuda_bf16.h>
#include <cstdint>

#define BATCH 4
#define NPTS 8192
#define KNN 16
#define NP_TOTAL (BATCH * NPTS)

typedef unsigned long long ull;

#define NCH1 33   // conv1: 259 ch -> 33 chunks of 8 ch (64 f)
#define NCH2 17   // conv2: 131 ch -> 17 chunks
#define ROWW 40   // A/B row stride in words (80 bf16 = 160B)
#define WSTR 132  // s_w row stride in floats
#define CHUNK_WORDS 10240   // per-chunk image: 2 halves x 128 rows x 40 words
#define NGROUPS (NP_TOTAL / 128)   // 256

__device__ float g_fcat1[NP_TOTAL * 260];   // [p][256 feat | 3 xyz | pad]
__device__ float g_fcat2[NP_TOTAL * 132];   // [p][128 feat | 3 xyz | pad]
__device__ float g_f2[NP_TOTAL * 128];
__device__ uint32_t g_B1[NCH1 * CHUNK_WORDS];
__device__ uint32_t g_B2[NCH2 * CHUNK_WORDS];
__device__ uint32_t g_A[(size_t)NGROUPS * NCH1 * CHUNK_WORDS];   // A scratch (reused)
__device__ float g_w1t[128 * 128];
__device__ float g_w2t[128 * 64];

__device__ __forceinline__ float lrelu(float v) { return v >= 0.f ? v : 0.1f * v; }
__device__ __forceinline__ ull ffma2(ull a, ull b, ull c) {
    ull d; asm("fma.rn.f32x2 %0, %1, %2, %3;" : "=l"(d) : "l"(a), "l"(b), "l"(c)); return d;
}
__device__ __forceinline__ ull dup2(float x) {
    ull d; asm("mov.b64 %0, {%1, %1};" : "=l"(d) : "f"(x)); return d;
}
__device__ __forceinline__ float2 unpk(ull v) {
    float2 r; asm("mov.b64 {%0, %1}, %2;" : "=f"(r.x), "=f"(r.y) : "l"(v)); return r;
}
__device__ __forceinline__ uint32_t pack_bf16(float a, float b) {
    __nv_bfloat162 h = __floats2bfloat162_rn(a, b);
    return *(uint32_t*)&h;
}
__device__ __forceinline__ float bf16r(float x) {
    return __bfloat162float(__float2bfloat16_rn(x));
}
__device__ __forceinline__ uint32_t s2u(const void* p) {
    uint32_t a;
    asm("{ .reg .u64 t; cvta.to.shared.u64 t, %1; cvt.u32.u64 %0, t; }" : "=r"(a) : "l"(p));
    return a;
}
__device__ __forceinline__ void cp16(uint32_t dst, const void* src) {
    asm volatile("cp.async.cg.shared.global [%0], [%1], 16;" :: "r"(dst), "l"(src));
}

__device__ __forceinline__ void mma_bf16(float* c, uint32_t a0, uint32_t a1,
                                         uint32_t a2, uint32_t a3,
                                         uint32_t b0, uint32_t b1) {
    asm volatile(
        "mma.sync.aligned.m16n8k16.row.col.f32.bf16.bf16.f32 "
        "{%0,%1,%2,%3}, {%4,%5,%6,%7}, {%8,%9}, {%0,%1,%2,%3};"
        : "+f"(c[0]), "+f"(c[1]), "+f"(c[2]), "+f"(c[3])
        : "r"(a0), "r"(a1), "r"(a2), "r"(a3), "r"(b0), "r"(b1));
}

// ---------------- transpose (launch #1) ------------------------------------------
__global__ void transpose_feat(const float* __restrict__ feat) {
    __shared__ float tile[32][33];
    int b = blockIdx.z;
    int n0 = blockIdx.x * 32, c0 = blockIdx.y * 32;
    int x = threadIdx.x, y = threadIdx.y;
    tile[y][x] = feat[((size_t)b * 256 + c0 + y) * NPTS + n0 + x];
    __syncthreads();
    g_fcat1[((size_t)(b * NPTS + n0 + y)) * 260 + c0 + x] = tile[x][y];
}

// col layout per k16 sub: pos(k) = (k&1) | (((k>>1)&3)<<2) | (((k>>3)&1)<<1)
__device__ __forceinline__ float fetch_w(const float* wl, int Freal, int CIN, int n,
                                         int ci, int col) {
    if (col >= 64) return 0.f;
    int s = col >> 4, pos = col & 15;
    int k = (pos & 1) | (((pos >> 2) & 3) << 1) | (((pos >> 1) & 1) << 3);
    int f = ci * 64 + s * 16 + k;
    int c = f >> 3, m = f & 7;
    if (c >= CIN + 3) return 0.f;
    int co = (c < CIN) ? c + 3 : c - CIN;
    return wl[n * Freal + co * 8 + m];
}

// ---------------- merged prep (launch #2) -----------------------------------------
__global__ void prep_all(const float* __restrict__ xyz,
                         const float* __restrict__ wl1, const float* __restrict__ wl2,
                         const float* __restrict__ wm1, const float* __restrict__ wm2) {
    int i = blockIdx.x * blockDim.x + threadIdx.x;
    if (i < 128 * 128) { int c = i >> 7, o = i & 127; g_w1t[i] = wm1[o * 128 + c]; }
    if (i < 128 * 64)  { int o = i >> 6, j = i & 63;  g_w2t[i] = wm2[j * 128 + o]; }
    if (i < NP_TOTAL * 3) {
        int p = i / 3, d = i - p * 3;
        int b = p >> 13, n = p & (NPTS - 1);
        float v = xyz[((size_t)b * 3 + d) * NPTS + n];
        g_fcat1[(size_t)p * 260 + 256 + d] = v;
        g_fcat2[(size_t)p * 132 + 128 + d] = v;
        if (d == 0) {
            g_fcat1[(size_t)p * 260 + 259] = 0.f;
            g_fcat2[(size_t)p * 132 + 131] = 0.f;
        }
    }
    if (i < NCH1 * CHUNK_WORDS) {
        int ci = i / CHUNK_WORDS, r = i % CHUNK_WORDS;
        int h = r / 5120, r2 = r % 5120;
        int n = r2 / ROWW, wc = r2 % ROWW;
        float v0 = fetch_w(wl1, 2072, 256, n, ci, 2 * wc);
        float v1 = fetch_w(wl1, 2072, 256, n, ci, 2 * wc + 1);
        float h0 = bf16r(v0), h1 = bf16r(v1);
        g_B1[i] = h ? pack_bf16(v0 - h0, v1 - h1) : pack_bf16(h0, h1);
    }
    if (i < NCH2 * CHUNK_WORDS) {
        int ci = i / CHUNK_WORDS, r = i % CHUNK_WORDS;
        int h = r / 5120, r2 = r % 5120;
        int n = r2 / ROWW, wc = r2 % ROWW;
        float v0 = fetch_w(wl2, 1048, 128, n, ci, 2 * wc);
        float v1 = fetch_w(wl2, 1048, 128, n, ci, 2 * wc + 1);
        float h0 = bf16r(v0), h1 = bf16r(v1);
        g_B2[i] = h ? pack_bf16(v0 - h0, v1 - h1) : pack_bf16(h0, h1);
    }
}

// ---------------- producer: gather + weight-net -> A images in gmem ---------------
#define P_OFF_W   0
#define P_OFF_NBR 16896
#define P_OFF_CX  18944
#define P_DYN_BYTES (19328 * 4)

template <int CIN, int STRIDE_IN, int NCHUNK>
__global__ void __launch_bounds__(256, 2)
producer(const float* __restrict__ fcat, const int* __restrict__ knn,
         const float* __restrict__ w_wn, const float* __restrict__ b_wn,
         uint32_t* __restrict__ gA) {
    constexpr int CIN3 = CIN + 3;

    extern __shared__ float dyn[];
    float* s_w   = dyn + P_OFF_W;
    int*   s_nbr = (int*)(dyn + P_OFF_NBR);
    float* s_cx  = dyn + P_OFF_CX;

    __shared__ float s_wn[24];
    __shared__ float s_bwn[8];

    const int tid  = threadIdx.x;
    const int wid  = tid >> 5, lane = tid & 31;
    const int base = blockIdx.x * 128;
    const int boff = (base >> 13) << 13;

    if (tid < 24) s_wn[tid] = w_wn[tid];
    if (tid < 8)  s_bwn[tid] = b_wn[tid];
    if (tid < 128) {
        const float* cp = fcat + (size_t)(base + tid) * STRIDE_IN + CIN;
        s_cx[tid * 3 + 0] = cp[0];
        s_cx[tid * 3 + 1] = cp[1];
        s_cx[tid * 3 + 2] = cp[2];
    }
#pragma unroll
    for (int r = 0; r < 8; ++r) {
        int id = tid + r * 256;
        int pt = id >> 4, k = id & 15;
        s_nbr[id] = boff + knn[(size_t)(base + pt) * KNN + k];
    }
    __syncthreads();

#pragma unroll
    for (int r = 0; r < 8; ++r) {
        int id = tid + r * 256;
        int pt = id >> 4, k = id & 15;
        int j = s_nbr[id];
        const float* nx = fcat + (size_t)j * STRIDE_IN + CIN;
        float px = nx[0] - s_cx[pt * 3 + 0];
        float py = nx[1] - s_cx[pt * 3 + 1];
        float pz = nx[2] - s_cx[pt * 3 + 2];
#pragma unroll
        for (int m = 0; m < 8; ++m) {
            float v = s_wn[m * 3 + 0] * px + s_wn[m * 3 + 1] * py +
                      s_wn[m * 3 + 2] * pz + s_bwn[m];
            s_w[pt * WSTR + k * 8 + m] = lrelu(v);
        }
    }
    __syncthreads();

    const int ptl  = lane >> 1;
    const int pt_p = wid * 16 + ptl;
    const int quad = lane & 1;
    int nb[16];
    {
        const int4* q = (const int4*)(s_nbr + pt_p * 16);
        int4 n0 = q[0], n1 = q[1], n2 = q[2], n3 = q[3];
        nb[0]=n0.x; nb[1]=n0.y; nb[2]=n0.z; nb[3]=n0.w;
        nb[4]=n1.x; nb[5]=n1.y; nb[6]=n1.z; nb[7]=n1.w;
        nb[8]=n2.x; nb[9]=n2.y; nb[10]=n2.z; nb[11]=n2.w;
        nb[12]=n3.x; nb[13]=n3.y; nb[14]=n3.z; nb[15]=n3.w;
    }
    const float* wp_p = s_w + pt_p * WSTR;

    for (int ci = 0; ci < NCHUNK; ++ci) {
        const int cbase = ci * 8 + quad * 4;
        ull pa[16];
#pragma unroll
        for (int i = 0; i < 16; ++i) pa[i] = 0ULL;
        if (cbase < CIN3) {
            const float* fp = fcat + cbase;
#pragma unroll
            for (int k = 0; k < 16; ++k) {
                float4 f4 = __ldg((const float4*)(fp + (size_t)nb[k] * STRIDE_IN));
                ulonglong2 w01 = *(const ulonglong2*)(wp_p + k * 8);
                ulonglong2 w23 = *(const ulonglong2*)(wp_p + k * 8 + 4);
                ull f0 = dup2(f4.x), f1 = dup2(f4.y), f2 = dup2(f4.z), f3 = dup2(f4.w);
                pa[0]  = ffma2(f0, w01.x, pa[0]);
                pa[1]  = ffma2(f0, w01.y, pa[1]);
                pa[2]  = ffma2(f0, w23.x, pa[2]);
                pa[3]  = ffma2(f0, w23.y, pa[3]);
                pa[4]  = ffma2(f1, w01.x, pa[4]);
                pa[5]  = ffma2(f1, w01.y, pa[5]);
                pa[6]  = ffma2(f1, w23.x, pa[6]);
                pa[7]  = ffma2(f1, w23.y, pa[7]);
                pa[8]  = ffma2(f2, w01.x, pa[8]);
                pa[9]  = ffma2(f2, w01.y, pa[9]);
                pa[10] = ffma2(f2, w23.x, pa[10]);
                pa[11] = ffma2(f2, w23.y, pa[11]);
                pa[12] = ffma2(f3, w01.x, pa[12]);
                pa[13] = ffma2(f3, w01.y, pa[13]);
                pa[14] = ffma2(f3, w23.x, pa[14]);
                pa[15] = ffma2(f3, w23.y, pa[15]);
            }
        }
        uint32_t hiw[16], low[16];
#pragma unroll
        for (int g2 = 0; g2 < 2; ++g2) {
#pragma unroll
            for (int mp = 0; mp < 4; ++mp) {
                float2 va = unpk(pa[g2 * 8 + mp]);
                float2 vb = unpk(pa[g2 * 8 + 4 + mp]);
                float ha0 = bf16r(va.x), ha1 = bf16r(va.y);
                float hb0 = bf16r(vb.x), hb1 = bf16r(vb.y);
                hiw[g2 * 8 + mp * 2 + 0] = pack_bf16(ha0, ha1);
                hiw[g2 * 8 + mp * 2 + 1] = pack_bf16(hb0, hb1);
                low[g2 * 8 + mp * 2 + 0] = pack_bf16(va.x - ha0, va.y - ha1);
                low[g2 * 8 + mp * 2 + 1] = pack_bf16(vb.x - hb0, vb.y - hb1);
            }
        }
        uint32_t* outp = gA + ((size_t)blockIdx.x * NCHUNK + ci) * CHUNK_WORDS
                       + pt_p * ROWW + quad * 16;
        ((uint4*)outp)[0] = ((uint4*)hiw)[0];
        ((uint4*)outp)[1] = ((uint4*)hiw)[1];
        ((uint4*)outp)[2] = ((uint4*)hiw)[2];
        ((uint4*)outp)[3] = ((uint4*)hiw)[3];
        uint32_t* outl = outp + 5120;
        ((uint4*)outl)[0] = ((uint4*)low)[0];
        ((uint4*)outl)[1] = ((uint4*)low)[1];
        ((uint4*)outl)[2] = ((uint4*)low)[2];
        ((uint4*)outl)[3] = ((uint4*)low)[3];
    }
}

// ---------------- GEMM: 512 threads, cp.async pipelined bf16 3-term MMA -----------
#define G_OFF_A0 0
#define G_OFF_A1 10240
#define G_OFF_B0 20480
#define G_OFF_B1 30720
#define G_OFF_BIAS 40960
#define G_DYN_BYTES (41088 * 4)

template <int OUT_STRIDE, int NCHUNK>
__global__ void __launch_bounds__(512, 1)
gemm_mma(const uint32_t* __restrict__ gA, const uint32_t* __restrict__ gB,
         const float* __restrict__ b_lin, float* __restrict__ out) {
    extern __shared__ float dyn[];
    uint32_t* smw = (uint32_t*)dyn;
    float* s_bias = dyn + G_OFF_BIAS;

    const int tid  = threadIdx.x;
    const int wid  = tid >> 5, lane = tid & 31;
    const int g    = lane >> 2, t = lane & 3;
    const int base = blockIdx.x * 128;

    if (tid < 128) s_bias[tid] = b_lin[tid];

    const uint32_t aBuf[2] = { s2u(smw + G_OFF_A0), s2u(smw + G_OFF_A1) };
    const uint32_t bBuf[2] = { s2u(smw + G_OFF_B0), s2u(smw + G_OFF_B1) };

    auto copy_chunk = [&](int ci) {
        const int bsel = ci & 1;
        const uint4* srcA = (const uint4*)(gA + ((size_t)blockIdx.x * NCHUNK + ci) * CHUNK_WORDS);
        const uint4* srcB = (const uint4*)(gB + (size_t)ci * CHUNK_WORDS);
        const uint32_t dA = aBuf[bsel], dB = bBuf[bsel];
#pragma unroll
        for (int r = 0; r < 5; ++r) {
            int i = tid + r * 512;
            cp16(dA + i * 16, srcA + i);
            cp16(dB + i * 16, srcB + i);
        }
        asm volatile("cp.async.commit_group;");
    };

    copy_chunk(0);

    float acc[32];
#pragma unroll
    for (int i = 0; i < 32; ++i) acc[i] = 0.f;

    // 16 warps: warp tile = rows rt*32..+31, cols ch*32..+31
    const int rt = wid & 3, ch = wid >> 2;
    const int rowA = rt * 32 + g;

    for (int ci = 0; ci < NCHUNK; ++ci) {
        const bool more = (ci + 1 < NCHUNK);
        if (more) {
            copy_chunk(ci + 1);
            asm volatile("cp.async.wait_group 1;");
        } else {
            asm volatile("cp.async.wait_group 0;");
        }
        __syncthreads();

        const uint32_t* sAH = smw + ((ci & 1) ? G_OFF_A1 : G_OFF_A0);
        const uint32_t* sAL = sAH + 5120;
        const uint32_t* sB  = smw + ((ci & 1) ? G_OFF_B1 : G_OFF_B0);
#pragma unroll
        for (int s = 0; s < 4; ++s) {
            const int off = s * 8 + 2 * t;
            uint2 ah0 = *(const uint2*)(sAH + (rowA)      * ROWW + off);
            uint2 ah1 = *(const uint2*)(sAH + (rowA + 8)  * ROWW + off);
            uint2 ah2 = *(const uint2*)(sAH + (rowA + 16) * ROWW + off);
            uint2 ah3 = *(const uint2*)(sAH + (rowA + 24) * ROWW + off);
            uint2 al0 = *(const uint2*)(sAL + (rowA)      * ROWW + off);
            uint2 al1 = *(const uint2*)(sAL + (rowA + 8)  * ROWW + off);
            uint2 al2 = *(const uint2*)(sAL + (rowA + 16) * ROWW + off);
            uint2 al3 = *(const uint2*)(sAL + (rowA + 24) * ROWW + off);
#pragma unroll
            for (int nt = 0; nt < 4; ++nt) {
                const int brow = ch * 32 + nt * 8 + g;
                uint2 bh = *(const uint2*)(sB + brow * ROWW + off);
                uint2 bl = *(const uint2*)(sB + 5120 + brow * ROWW + off);
                float* C0 = acc + nt * 4;
                float* C1 = acc + 16 + nt * 4;
                mma_bf16(C0, ah0.x, ah1.x, ah0.y, ah1.y, bh.x, bh.y);
                mma_bf16(C0, ah0.x, ah1.x, ah0.y, ah1.y, bl.x, bl.y);
                mma_bf16(C0, al0.x, al1.x, al0.y, al1.y, bh.x, bh.y);
                mma_bf16(C1, ah2.x, ah3.x, ah2.y, ah3.y, bh.x, bh.y);
                mma_bf16(C1, ah2.x, ah3.x, ah2.y, ah3.y, bl.x, bl.y);
                mma_bf16(C1, al2.x, al3.x, al2.y, al3.y, bh.x, bh.y);
            }
        }
        __syncthreads();
    }

#pragma unroll
    for (int mt = 0; mt < 2; ++mt) {
        const int r0 = base + rt * 32 + mt * 16 + g;
#pragma unroll
        for (int nt = 0; nt < 4; ++nt) {
            const int col = ch * 32 + nt * 8 + 2 * t;
            float b0 = s_bias[col], b1 = s_bias[col + 1];
            const float* C = acc + mt * 16 + nt * 4;
            float2 r01 = make_float2(lrelu(C[0] + b0), lrelu(C[1] + b1));
            float2 r23 = make_float2(lrelu(C[2] + b0), lrelu(C[3] + b1));
            *(float2*)(out + (size_t)r0 * OUT_STRIDE + col) = r01;
            *(float2*)(out + (size_t)(r0 + 8) * OUT_STRIDE + col) = r23;
        }
    }
}

// ---------------- MLP head --------------------------------------------------------
__global__ void mlp_kernel(const float* __restrict__ w_last, const float* __restrict__ b1,
                           const float* __restrict__ b2, const float* __restrict__ blast,
                           float* __restrict__ out) {
    __shared__ float s_f[16 * 128];
    __shared__ float s_h1[16 * 128];
    __shared__ float s_h2[16 * 64];
    const int tid = threadIdx.x;
    const int p0  = blockIdx.x * 16;

    for (int i = tid; i < 16 * 128; i += 256) s_f[i] = g_f2[(size_t)p0 * 128 + i];
    __syncthreads();
    {
        int o = tid & 127, tg = tid >> 7;
        float acc[8];
#pragma unroll
        for (int i = 0; i < 8; ++i) acc[i] = 0.f;
        for (int c = 0; c < 128; ++c) {
            float wv = g_w1t[c * 128 + o];
#pragma unroll
            for (int i = 0; i < 8; ++i) acc[i] += s_f[(tg * 8 + i) * 128 + c] * wv;
        }
        float bb = b1[o];
#pragma unroll
        for (int i = 0; i < 8; ++i) s_h1[(tg * 8 + i) * 128 + o] = lrelu(acc[i] + bb);
    }
    __syncthreads();
    {
        int jj = tid & 63, tg = tid >> 6;
        float acc[4];
#pragma unroll
        for (int i = 0; i < 4; ++i) acc[i] = 0.f;
        for (int c = 0; c < 128; ++c) {
            float wv = g_w2t[c * 64 + jj];
#pragma unroll
            for (int i = 0; i < 4; ++i) acc[i] += s_h1[(tg * 4 + i) * 128 + c] * wv;
        }
        float bb = b2[jj];
#pragma unroll
        for (int i = 0; i < 4; ++i) s_h2[(tg * 4 + i) * 64 + jj] = lrelu(acc[i] + bb);
    }
    __syncthreads();

    const int b = p0 >> 13, n0 = p0 & (NPTS - 1);
    for (int i = tid; i < 16 * 64; i += 256) {
        int t2 = i & 15, jj = i >> 4;
        out[((size_t)(b * 64 + jj)) * NPTS + n0 + t2] = s_h2[t2 * 64 + jj];
    }
    if (tid < 48) {
        int t2 = tid & 15, d = tid >> 4;
        float acc = 0.f;
#pragma unroll 8
        for (int jj = 0; jj < 64; ++jj) acc += w_last[d * 64 + jj] * s_h2[t2 * 64 + jj];
        out[(size_t)BATCH * 64 * NPTS + ((size_t)(b * 3 + d)) * NPTS + n0 + t2] = acc + blast[d];
    }
}

// ---------------- launch ------------------------------------------------------------
extern "C" void kernel_launch(void* const* d_in, const int* in_sizes, int n_in,
                              void* d_out, int out_size) {
    const float* xyz    = (const float*)d_in[0];
    const float* feat   = (const float*)d_in[1];
    const int*   knn    = (const int*)d_in[2];
    const float* w_wn1  = (const float*)d_in[3];
    const float* b_wn1  = (const float*)d_in[4];
    const float* w_lin1 = (const float*)d_in[5];
    const float* b_lin1 = (const float*)d_in[6];
    const float* w_wn2  = (const float*)d_in[7];
    const float* b_wn2  = (const float*)d_in[8];
    const float* w_lin2 = (const float*)d_in[9];
    const float* b_lin2 = (const float*)d_in[10];
    const float* w_mlp1 = (const float*)d_in[11];
    const float* b_mlp1 = (const float*)d_in[12];
    const float* w_mlp2 = (const float*)d_in[13];
    const float* b_mlp2 = (const float*)d_in[14];
    const float* w_last = (const float*)d_in[15];
    const float* b_last = (const float*)d_in[16];
    float* out = (float*)d_out;

    void *p_fcat1, *p_fcat2, *p_f2, *p_B1, *p_B2, *p_A;
    cudaGetSymbolAddress(&p_fcat1, g_fcat1);
    cudaGetSymbolAddress(&p_fcat2, g_fcat2);
    cudaGetSymbolAddress(&p_f2, g_f2);
    cudaGetSymbolAddress(&p_B1, g_B1);
    cudaGetSymbolAddress(&p_B2, g_B2);
    cudaGetSymbolAddress(&p_A, g_A);

    {
        dim3 tb(32, 32);
        dim3 tg(NPTS / 32, 256 / 32, BATCH);
        transpose_feat<<<tg, tb>>>(feat);
    }
    prep_all<<<(NCH1 * CHUNK_WORDS + 255) / 256, 256>>>(xyz, w_lin1, w_lin2, w_mlp1, w_mlp2);

    cudaFuncSetAttribute(producer<256, 260, NCH1>,
                         cudaFuncAttributeMaxDynamicSharedMemorySize, P_DYN_BYTES);
    producer<256, 260, NCH1><<<NGROUPS, 256, P_DYN_BYTES>>>(
        (const float*)p_fcat1, knn, w_wn1, b_wn1, (uint32_t*)p_A);

    cudaFuncSetAttribute(gemm_mma<132, NCH1>,
                         cudaFuncAttributeMaxDynamicSharedMemorySize, G_DYN_BYTES);
    gemm_mma<132, NCH1><<<NGROUPS, 512, G_DYN_BYTES>>>(
        (const uint32_t*)p_A, (const uint32_t*)p_B1, b_lin1, (float*)p_fcat2);

    cudaFuncSetAttribute(producer<128, 132, NCH2>,
                         cudaFuncAttributeMaxDynamicSharedMemorySize, P_DYN_BYTES);
    producer<128, 132, NCH2><<<NGROUPS, 256, P_DYN_BYTES>>>(
        (const float*)p_fcat2, knn, w_wn2, b_wn2, (uint32_t*)p_A);

    cudaFuncSetAttribute(gemm_mma<128, NCH2>,
                         cudaFuncAttributeMaxDynamicSharedMemorySize, G_DYN_BYTES);
    gemm_mma<128, NCH2><<<NGROUPS, 512, G_DYN_BYTES>>>(
        (const uint32_t*)p_A, (const uint32_t*)p_B2, b_lin2, (float*)p_f2);

    mlp_kernel<<<NP_TOTAL / 16, 256>>>(w_last, b_mlp1, b_mlp2, b_last, out);
}

// round 10
// speedup vs baseline: 1.3241x; 1.0087x over previous
#include <cuda_runtime.h>
#include <cuda_bf16.h>
#include <cstdint>

#define BATCH 4
#define NPTS 8192
#define KNN 16
#define NP_TOTAL (BATCH * NPTS)

typedef unsigned long long ull;

#define NCH1 33   // conv1: 259 ch -> 33 chunks of 8 ch (64 f)
#define NCH2 17   // conv2: 131 ch -> 17 chunks
#define ROWW 40   // A/B row stride in words (80 bf16 = 160B)
#define WSTR 132  // s_w row stride in floats
#define CHUNK_WORDS 10240   // per-chunk image: 2 halves x 128 rows x 40 words
#define NGROUPS (NP_TOTAL / 128)   // 256

__device__ float g_fcat1[NP_TOTAL * 260];   // [p][256 feat | 3 xyz | pad]
__device__ float g_fcat2[NP_TOTAL * 132];   // [p][128 feat | 3 xyz | pad]
__device__ float g_f2[NP_TOTAL * 128];
__device__ uint32_t g_B1[NCH1 * CHUNK_WORDS];
__device__ uint32_t g_B2[NCH2 * CHUNK_WORDS];
__device__ uint32_t g_A[(size_t)NGROUPS * NCH1 * CHUNK_WORDS];   // A scratch (reused)
__device__ float g_w1t[128 * 128];
__device__ float g_w2t[128 * 64];

__device__ __forceinline__ float lrelu(float v) { return v >= 0.f ? v : 0.1f * v; }
__device__ __forceinline__ ull ffma2(ull a, ull b, ull c) {
    ull d; asm("fma.rn.f32x2 %0, %1, %2, %3;" : "=l"(d) : "l"(a), "l"(b), "l"(c)); return d;
}
__device__ __forceinline__ ull dup2(float x) {
    ull d; asm("mov.b64 %0, {%1, %1};" : "=l"(d) : "f"(x)); return d;
}
__device__ __forceinline__ float2 unpk(ull v) {
    float2 r; asm("mov.b64 {%0, %1}, %2;" : "=f"(r.x), "=f"(r.y) : "l"(v)); return r;
}
__device__ __forceinline__ uint32_t pack_bf16(float a, float b) {
    __nv_bfloat162 h = __floats2bfloat162_rn(a, b);
    return *(uint32_t*)&h;
}
__device__ __forceinline__ float bf16r(float x) {
    return __bfloat162float(__float2bfloat16_rn(x));
}
__device__ __forceinline__ uint32_t s2u(const void* p) {
    uint32_t a;
    asm("{ .reg .u64 t; cvta.to.shared.u64 t, %1; cvt.u32.u64 %0, t; }" : "=r"(a) : "l"(p));
    return a;
}
__device__ __forceinline__ void cp16(uint32_t dst, const void* src) {
    asm volatile("cp.async.cg.shared.global [%0], [%1], 16;" :: "r"(dst), "l"(src));
}

__device__ __forceinline__ void mma_bf16(float* c, uint32_t a0, uint32_t a1,
                                         uint32_t a2, uint32_t a3,
                                         uint32_t b0, uint32_t b1) {
    asm volatile(
        "mma.sync.aligned.m16n8k16.row.col.f32.bf16.bf16.f32 "
        "{%0,%1,%2,%3}, {%4,%5,%6,%7}, {%8,%9}, {%0,%1,%2,%3};"
        : "+f"(c[0]), "+f"(c[1]), "+f"(c[2]), "+f"(c[3])
        : "r"(a0), "r"(a1), "r"(a2), "r"(a3), "r"(b0), "r"(b1));
}

// ---------------- transpose (launch #1) ------------------------------------------
__global__ void transpose_feat(const float* __restrict__ feat) {
    __shared__ float tile[32][33];
    int b = blockIdx.z;
    int n0 = blockIdx.x * 32, c0 = blockIdx.y * 32;
    int x = threadIdx.x, y = threadIdx.y;
    tile[y][x] = feat[((size_t)b * 256 + c0 + y) * NPTS + n0 + x];
    __syncthreads();
    g_fcat1[((size_t)(b * NPTS + n0 + y)) * 260 + c0 + x] = tile[x][y];
}

// col layout per k16 sub: pos(k) = (k&1) | (((k>>1)&3)<<2) | (((k>>3)&1)<<1)
__device__ __forceinline__ float fetch_w(const float* wl, int Freal, int CIN, int n,
                                         int ci, int col) {
    if (col >= 64) return 0.f;
    int s = col >> 4, pos = col & 15;
    int k = (pos & 1) | (((pos >> 2) & 3) << 1) | (((pos >> 1) & 1) << 3);
    int f = ci * 64 + s * 16 + k;
    int c = f >> 3, m = f & 7;
    if (c >= CIN + 3) return 0.f;
    int co = (c < CIN) ? c + 3 : c - CIN;
    return wl[n * Freal + co * 8 + m];
}

// ---------------- merged prep (launch #2) -----------------------------------------
__global__ void prep_all(const float* __restrict__ xyz,
                         const float* __restrict__ wl1, const float* __restrict__ wl2,
                         const float* __restrict__ wm1, const float* __restrict__ wm2) {
    int i = blockIdx.x * blockDim.x + threadIdx.x;
    if (i < 128 * 128) { int c = i >> 7, o = i & 127; g_w1t[i] = wm1[o * 128 + c]; }
    if (i < 128 * 64)  { int o = i >> 6, j = i & 63;  g_w2t[i] = wm2[j * 128 + o]; }
    if (i < NP_TOTAL * 3) {
        int p = i / 3, d = i - p * 3;
        int b = p >> 13, n = p & (NPTS - 1);
        float v = xyz[((size_t)b * 3 + d) * NPTS + n];
        g_fcat1[(size_t)p * 260 + 256 + d] = v;
        g_fcat2[(size_t)p * 132 + 128 + d] = v;
        if (d == 0) {
            g_fcat1[(size_t)p * 260 + 259] = 0.f;
            g_fcat2[(size_t)p * 132 + 131] = 0.f;
        }
    }
    if (i < NCH1 * CHUNK_WORDS) {
        int ci = i / CHUNK_WORDS, r = i % CHUNK_WORDS;
        int h = r / 5120, r2 = r % 5120;
        int n = r2 / ROWW, wc = r2 % ROWW;
        float v0 = fetch_w(wl1, 2072, 256, n, ci, 2 * wc);
        float v1 = fetch_w(wl1, 2072, 256, n, ci, 2 * wc + 1);
        float h0 = bf16r(v0), h1 = bf16r(v1);
        g_B1[i] = h ? pack_bf16(v0 - h0, v1 - h1) : pack_bf16(h0, h1);
    }
    if (i < NCH2 * CHUNK_WORDS) {
        int ci = i / CHUNK_WORDS, r = i % CHUNK_WORDS;
        int h = r / 5120, r2 = r % 5120;
        int n = r2 / ROWW, wc = r2 % ROWW;
        float v0 = fetch_w(wl2, 1048, 128, n, ci, 2 * wc);
        float v1 = fetch_w(wl2, 1048, 128, n, ci, 2 * wc + 1);
        float h0 = bf16r(v0), h1 = bf16r(v1);
        g_B2[i] = h ? pack_bf16(v0 - h0, v1 - h1) : pack_bf16(h0, h1);
    }
}

// ---------------- producer: gather + weight-net -> A images in gmem ---------------
#define P_OFF_W   0
#define P_OFF_NBR 16896
#define P_OFF_CX  18944
#define P_DYN_BYTES (19328 * 4)

template <int CIN, int STRIDE_IN, int NCHUNK>
__global__ void __launch_bounds__(256, 2)
producer(const float* __restrict__ fcat, const int* __restrict__ knn,
         const float* __restrict__ w_wn, const float* __restrict__ b_wn,
         uint32_t* __restrict__ gA) {
    constexpr int CIN3 = CIN + 3;

    extern __shared__ float dyn[];
    float* s_w   = dyn + P_OFF_W;
    int*   s_nbr = (int*)(dyn + P_OFF_NBR);
    float* s_cx  = dyn + P_OFF_CX;

    __shared__ float s_wn[24];
    __shared__ float s_bwn[8];

    const int tid  = threadIdx.x;
    const int wid  = tid >> 5, lane = tid & 31;
    const int base = blockIdx.x * 128;
    const int boff = (base >> 13) << 13;

    if (tid < 24) s_wn[tid] = w_wn[tid];
    if (tid < 8)  s_bwn[tid] = b_wn[tid];
    if (tid < 128) {
        const float* cp = fcat + (size_t)(base + tid) * STRIDE_IN + CIN;
        s_cx[tid * 3 + 0] = cp[0];
        s_cx[tid * 3 + 1] = cp[1];
        s_cx[tid * 3 + 2] = cp[2];
    }
#pragma unroll
    for (int r = 0; r < 8; ++r) {
        int id = tid + r * 256;
        int pt = id >> 4, k = id & 15;
        s_nbr[id] = boff + knn[(size_t)(base + pt) * KNN + k];
    }
    __syncthreads();

#pragma unroll
    for (int r = 0; r < 8; ++r) {
        int id = tid + r * 256;
        int pt = id >> 4, k = id & 15;
        int j = s_nbr[id];
        const float* nx = fcat + (size_t)j * STRIDE_IN + CIN;
        float px = nx[0] - s_cx[pt * 3 + 0];
        float py = nx[1] - s_cx[pt * 3 + 1];
        float pz = nx[2] - s_cx[pt * 3 + 2];
#pragma unroll
        for (int m = 0; m < 8; ++m) {
            float v = s_wn[m * 3 + 0] * px + s_wn[m * 3 + 1] * py +
                      s_wn[m * 3 + 2] * pz + s_bwn[m];
            s_w[pt * WSTR + k * 8 + m] = lrelu(v);
        }
    }
    __syncthreads();

    const int ptl  = lane >> 1;
    const int pt_p = wid * 16 + ptl;
    const int quad = lane & 1;
    int nb[16];
    {
        const int4* q = (const int4*)(s_nbr + pt_p * 16);
        int4 n0 = q[0], n1 = q[1], n2 = q[2], n3 = q[3];
        nb[0]=n0.x; nb[1]=n0.y; nb[2]=n0.z; nb[3]=n0.w;
        nb[4]=n1.x; nb[5]=n1.y; nb[6]=n1.z; nb[7]=n1.w;
        nb[8]=n2.x; nb[9]=n2.y; nb[10]=n2.z; nb[11]=n2.w;
        nb[12]=n3.x; nb[13]=n3.y; nb[14]=n3.z; nb[15]=n3.w;
    }
    const float* wp_p = s_w + pt_p * WSTR;

    for (int ci = 0; ci < NCHUNK; ++ci) {
        const int cbase = ci * 8 + quad * 4;
        ull pa[16];
#pragma unroll
        for (int i = 0; i < 16; ++i) pa[i] = 0ULL;
        if (cbase < CIN3) {
            const float* fp = fcat + cbase;
#pragma unroll
            for (int k = 0; k < 16; ++k) {
                float4 f4 = __ldg((const float4*)(fp + (size_t)nb[k] * STRIDE_IN));
                ulonglong2 w01 = *(const ulonglong2*)(wp_p + k * 8);
                ulonglong2 w23 = *(const ulonglong2*)(wp_p + k * 8 + 4);
                ull f0 = dup2(f4.x), f1 = dup2(f4.y), f2 = dup2(f4.z), f3 = dup2(f4.w);
                pa[0]  = ffma2(f0, w01.x, pa[0]);
                pa[1]  = ffma2(f0, w01.y, pa[1]);
                pa[2]  = ffma2(f0, w23.x, pa[2]);
                pa[3]  = ffma2(f0, w23.y, pa[3]);
                pa[4]  = ffma2(f1, w01.x, pa[4]);
                pa[5]  = ffma2(f1, w01.y, pa[5]);
                pa[6]  = ffma2(f1, w23.x, pa[6]);
                pa[7]  = ffma2(f1, w23.y, pa[7]);
                pa[8]  = ffma2(f2, w01.x, pa[8]);
                pa[9]  = ffma2(f2, w01.y, pa[9]);
                pa[10] = ffma2(f2, w23.x, pa[10]);
                pa[11] = ffma2(f2, w23.y, pa[11]);
                pa[12] = ffma2(f3, w01.x, pa[12]);
                pa[13] = ffma2(f3, w01.y, pa[13]);
                pa[14] = ffma2(f3, w23.x, pa[14]);
                pa[15] = ffma2(f3, w23.y, pa[15]);
            }
        }
        uint32_t hiw[16], low[16];
#pragma unroll
        for (int g2 = 0; g2 < 2; ++g2) {
#pragma unroll
            for (int mp = 0; mp < 4; ++mp) {
                float2 va = unpk(pa[g2 * 8 + mp]);
                float2 vb = unpk(pa[g2 * 8 + 4 + mp]);
                float ha0 = bf16r(va.x), ha1 = bf16r(va.y);
                float hb0 = bf16r(vb.x), hb1 = bf16r(vb.y);
                hiw[g2 * 8 + mp * 2 + 0] = pack_bf16(ha0, ha1);
                hiw[g2 * 8 + mp * 2 + 1] = pack_bf16(hb0, hb1);
                low[g2 * 8 + mp * 2 + 0] = pack_bf16(va.x - ha0, va.y - ha1);
                low[g2 * 8 + mp * 2 + 1] = pack_bf16(vb.x - hb0, vb.y - hb1);
            }
        }
        uint32_t* outp = gA + ((size_t)blockIdx.x * NCHUNK + ci) * CHUNK_WORDS
                       + pt_p * ROWW + quad * 16;
        ((uint4*)outp)[0] = ((uint4*)hiw)[0];
        ((uint4*)outp)[1] = ((uint4*)hiw)[1];
        ((uint4*)outp)[2] = ((uint4*)hiw)[2];
        ((uint4*)outp)[3] = ((uint4*)hiw)[3];
        uint32_t* outl = outp + 5120;
        ((uint4*)outl)[0] = ((uint4*)low)[0];
        ((uint4*)outl)[1] = ((uint4*)low)[1];
        ((uint4*)outl)[2] = ((uint4*)low)[2];
        ((uint4*)outl)[3] = ((uint4*)low)[3];
    }
}

// ---------------- GEMM: 512 threads, term-major MMA ordering ----------------------
#define G_OFF_A0 0
#define G_OFF_A1 10240
#define G_OFF_B0 20480
#define G_OFF_B1 30720
#define G_OFF_BIAS 40960
#define G_DYN_BYTES (41088 * 4)

template <int OUT_STRIDE, int NCHUNK>
__global__ void __launch_bounds__(512, 1)
gemm_mma(const uint32_t* __restrict__ gA, const uint32_t* __restrict__ gB,
         const float* __restrict__ b_lin, float* __restrict__ out) {
    extern __shared__ float dyn[];
    uint32_t* smw = (uint32_t*)dyn;
    float* s_bias = dyn + G_OFF_BIAS;

    const int tid  = threadIdx.x;
    const int wid  = tid >> 5, lane = tid & 31;
    const int g    = lane >> 2, t = lane & 3;
    const int base = blockIdx.x * 128;

    if (tid < 128) s_bias[tid] = b_lin[tid];

    const uint32_t aBuf[2] = { s2u(smw + G_OFF_A0), s2u(smw + G_OFF_A1) };
    const uint32_t bBuf[2] = { s2u(smw + G_OFF_B0), s2u(smw + G_OFF_B1) };

    auto copy_chunk = [&](int ci) {
        const int bsel = ci & 1;
        const uint4* srcA = (const uint4*)(gA + ((size_t)blockIdx.x * NCHUNK + ci) * CHUNK_WORDS);
        const uint4* srcB = (const uint4*)(gB + (size_t)ci * CHUNK_WORDS);
        const uint32_t dA = aBuf[bsel], dB = bBuf[bsel];
#pragma unroll
        for (int r = 0; r < 5; ++r) {
            int i = tid + r * 512;
            cp16(dA + i * 16, srcA + i);
            cp16(dB + i * 16, srcB + i);
        }
        asm volatile("cp.async.commit_group;");
    };

    copy_chunk(0);

    float acc[32];
#pragma unroll
    for (int i = 0; i < 32; ++i) acc[i] = 0.f;

    // 16 warps: warp tile = rows rt*32..+31, cols ch*32..+31
    const int rt = wid & 3, ch = wid >> 2;
    const int rowA = rt * 32 + g;

    for (int ci = 0; ci < NCHUNK; ++ci) {
        const bool more = (ci + 1 < NCHUNK);
        if (more) {
            copy_chunk(ci + 1);
            asm volatile("cp.async.wait_group 1;");
        } else {
            asm volatile("cp.async.wait_group 0;");
        }
        __syncthreads();

        const uint32_t* sAH = smw + ((ci & 1) ? G_OFF_A1 : G_OFF_A0);
        const uint32_t* sAL = sAH + 5120;
        const uint32_t* sB  = smw + ((ci & 1) ? G_OFF_B1 : G_OFF_B0);
#pragma unroll
        for (int s = 0; s < 4; ++s) {
            const int off = s * 8 + 2 * t;
            // hoist all fragments for this k16 slab
            uint2 ah0 = *(const uint2*)(sAH + (rowA)      * ROWW + off);
            uint2 ah1 = *(const uint2*)(sAH + (rowA + 8)  * ROWW + off);
            uint2 ah2 = *(const uint2*)(sAH + (rowA + 16) * ROWW + off);
            uint2 ah3 = *(const uint2*)(sAH + (rowA + 24) * ROWW + off);
            uint2 al0 = *(const uint2*)(sAL + (rowA)      * ROWW + off);
            uint2 al1 = *(const uint2*)(sAL + (rowA + 8)  * ROWW + off);
            uint2 al2 = *(const uint2*)(sAL + (rowA + 16) * ROWW + off);
            uint2 al3 = *(const uint2*)(sAL + (rowA + 24) * ROWW + off);
            uint2 bh[4], bl[4];
#pragma unroll
            for (int nt = 0; nt < 4; ++nt) {
                const int brow = ch * 32 + nt * 8 + g;
                bh[nt] = *(const uint2*)(sB + brow * ROWW + off);
                bl[nt] = *(const uint2*)(sB + 5120 + brow * ROWW + off);
            }
            // term-major ordering: same-accumulator MMAs are 8 apart
#pragma unroll
            for (int nt = 0; nt < 4; ++nt) {
                mma_bf16(acc + nt * 4,      ah0.x, ah1.x, ah0.y, ah1.y, bh[nt].x, bh[nt].y);
                mma_bf16(acc + 16 + nt * 4, ah2.x, ah3.x, ah2.y, ah3.y, bh[nt].x, bh[nt].y);
            }
#pragma unroll
            for (int nt = 0; nt < 4; ++nt) {
                mma_bf16(acc + nt * 4,      ah0.x, ah1.x, ah0.y, ah1.y, bl[nt].x, bl[nt].y);
                mma_bf16(acc + 16 + nt * 4, ah2.x, ah3.x, ah2.y, ah3.y, bl[nt].x, bl[nt].y);
            }
#pragma unroll
            for (int nt = 0; nt < 4; ++nt) {
                mma_bf16(acc + nt * 4,      al0.x, al1.x, al0.y, al1.y, bh[nt].x, bh[nt].y);
                mma_bf16(acc + 16 + nt * 4, al2.x, al3.x, al2.y, al3.y, bh[nt].x, bh[nt].y);
            }
        }
        __syncthreads();
    }

#pragma unroll
    for (int mt = 0; mt < 2; ++mt) {
        const int r0 = base + rt * 32 + mt * 16 + g;
#pragma unroll
        for (int nt = 0; nt < 4; ++nt) {
            const int col = ch * 32 + nt * 8 + 2 * t;
            float b0 = s_bias[col], b1 = s_bias[col + 1];
            const float* C = acc + mt * 16 + nt * 4;
            float2 r01 = make_float2(lrelu(C[0] + b0), lrelu(C[1] + b1));
            float2 r23 = make_float2(lrelu(C[2] + b0), lrelu(C[3] + b1));
            *(float2*)(out + (size_t)r0 * OUT_STRIDE + col) = r01;
            *(float2*)(out + (size_t)(r0 + 8) * OUT_STRIDE + col) = r23;
        }
    }
}

// ---------------- MLP head --------------------------------------------------------
__global__ void mlp_kernel(const float* __restrict__ w_last, const float* __restrict__ b1,
                           const float* __restrict__ b2, const float* __restrict__ blast,
                           float* __restrict__ out) {
    __shared__ float s_f[16 * 128];
    __shared__ float s_h1[16 * 128];
    __shared__ float s_h2[16 * 64];
    const int tid = threadIdx.x;
    const int p0  = blockIdx.x * 16;

    for (int i = tid; i < 16 * 128; i += 256) s_f[i] = g_f2[(size_t)p0 * 128 + i];
    __syncthreads();
    {
        int o = tid & 127, tg = tid >> 7;
        float acc[8];
#pragma unroll
        for (int i = 0; i < 8; ++i) acc[i] = 0.f;
        for (int c = 0; c < 128; ++c) {
            float wv = g_w1t[c * 128 + o];
#pragma unroll
            for (int i = 0; i < 8; ++i) acc[i] += s_f[(tg * 8 + i) * 128 + c] * wv;
        }
        float bb = b1[o];
#pragma unroll
        for (int i = 0; i < 8; ++i) s_h1[(tg * 8 + i) * 128 + o] = lrelu(acc[i] + bb);
    }
    __syncthreads();
    {
        int jj = tid & 63, tg = tid >> 6;
        float acc[4];
#pragma unroll
        for (int i = 0; i < 4; ++i) acc[i] = 0.f;
        for (int c = 0; c < 128; ++c) {
            float wv = g_w2t[c * 64 + jj];
#pragma unroll
            for (int i = 0; i < 4; ++i) acc[i] += s_h1[(tg * 4 + i) * 128 + c] * wv;
        }
        float bb = b2[jj];
#pragma unroll
        for (int i = 0; i < 4; ++i) s_h2[(tg * 4 + i) * 64 + jj] = lrelu(acc[i] + bb);
    }
    __syncthreads();

    const int b = p0 >> 13, n0 = p0 & (NPTS - 1);
    for (int i = tid; i < 16 * 64; i += 256) {
        int t2 = i & 15, jj = i >> 4;
        out[((size_t)(b * 64 + jj)) * NPTS + n0 + t2] = s_h2[t2 * 64 + jj];
    }
    if (tid < 48) {
        int t2 = tid & 15, d = tid >> 4;
        float acc = 0.f;
#pragma unroll 8
        for (int jj = 0; jj < 64; ++jj) acc += w_last[d * 64 + jj] * s_h2[t2 * 64 + jj];
        out[(size_t)BATCH * 64 * NPTS + ((size_t)(b * 3 + d)) * NPTS + n0 + t2] = acc + blast[d];
    }
}

// ---------------- launch ------------------------------------------------------------
extern "C" void kernel_launch(void* const* d_in, const int* in_sizes, int n_in,
                              void* d_out, int out_size) {
    const float* xyz    = (const float*)d_in[0];
    const float* feat   = (const float*)d_in[1];
    const int*   knn    = (const int*)d_in[2];
    const float* w_wn1  = (const float*)d_in[3];
    const float* b_wn1  = (const float*)d_in[4];
    const float* w_lin1 = (const float*)d_in[5];
    const float* b_lin1 = (const float*)d_in[6];
    const float* w_wn2  = (const float*)d_in[7];
    const float* b_wn2  = (const float*)d_in[8];
    const float* w_lin2 = (const float*)d_in[9];
    const float* b_lin2 = (const float*)d_in[10];
    const float* w_mlp1 = (const float*)d_in[11];
    const float* b_mlp1 = (const float*)d_in[12];
    const float* w_mlp2 = (const float*)d_in[13];
    const float* b_mlp2 = (const float*)d_in[14];
    const float* w_last = (const float*)d_in[15];
    const float* b_last = (const float*)d_in[16];
    float* out = (float*)d_out;

    void *p_fcat1, *p_fcat2, *p_f2, *p_B1, *p_B2, *p_A;
    cudaGetSymbolAddress(&p_fcat1, g_fcat1);
    cudaGetSymbolAddress(&p_fcat2, g_fcat2);
    cudaGetSymbolAddress(&p_f2, g_f2);
    cudaGetSymbolAddress(&p_B1, g_B1);
    cudaGetSymbolAddress(&p_B2, g_B2);
    cudaGetSymbolAddress(&p_A, g_A);

    {
        dim3 tb(32, 32);
        dim3 tg(NPTS / 32, 256 / 32, BATCH);
        transpose_feat<<<tg, tb>>>(feat);
    }
    prep_all<<<(NCH1 * CHUNK_WORDS + 255) / 256, 256>>>(xyz, w_lin1, w_lin2, w_mlp1, w_mlp2);

    cudaFuncSetAttribute(producer<256, 260, NCH1>,
                         cudaFuncAttributeMaxDynamicSharedMemorySize, P_DYN_BYTES);
    producer<256, 260, NCH1><<<NGROUPS, 256, P_DYN_BYTES>>>(
        (const float*)p_fcat1, knn, w_wn1, b_wn1, (uint32_t*)p_A);

    cudaFuncSetAttribute(gemm_mma<132, NCH1>,
                         cudaFuncAttributeMaxDynamicSharedMemorySize, G_DYN_BYTES);
    gemm_mma<132, NCH1><<<NGROUPS, 512, G_DYN_BYTES>>>(
        (const uint32_t*)p_A, (const uint32_t*)p_B1, b_lin1, (float*)p_fcat2);

    cudaFuncSetAttribute(producer<128, 132, NCH2>,
                         cudaFuncAttributeMaxDynamicSharedMemorySize, P_DYN_BYTES);
    producer<128, 132, NCH2><<<NGROUPS, 256, P_DYN_BYTES>>>(
        (const float*)p_fcat2, knn, w_wn2, b_wn2, (uint32_t*)p_A);

    cudaFuncSetAttribute(gemm_mma<128, NCH2>,
                         cudaFuncAttributeMaxDynamicSharedMemorySize, G_DYN_BYTES);
    gemm_mma<128, NCH2><<<NGROUPS, 512, G_DYN_BYTES>>>(
        (const uint32_t*)p_A, (const uint32_t*)p_B2, b_lin2, (float*)p_f2);

    mlp_kernel<<<NP_TOTAL / 16, 256>>>(w_last, b_mlp1, b_mlp2, b_last, out);
}